// round 2
// baseline (speedup 1.0000x reference)
#include <cuda_runtime.h>
#include <cstdint>

// ---------------------------------------------------------------------------
// Problem constants
//   B=2, S=2048, D_MODEL=2048, N_HEADS=32, N_KV_HEADS=8, D_HEAD=64
//   tokens T = B*S = 4096
// ---------------------------------------------------------------------------
#define T_TOK 4096
#define DMODEL 2048
#define NH 32
#define NKV 8
#define DH 64
#define SEQ 2048

// Scratch (allocation-free: __device__ globals)
__device__ float g_Q[(size_t)T_TOK * (NH * DH)];    // [token, 2048]
__device__ float g_K[(size_t)T_TOK * (NKV * DH)];   // [token, 512]
__device__ float g_V[(size_t)T_TOK * (NKV * DH)];   // [token, 512]
__device__ float g_AO[(size_t)T_TOK * (NH * DH)];   // [token, 2048]

// ---------------------------------------------------------------------------
// SGEMM NT:  C[M,N] = A[M,K] * B[N,K]^T     (A,B,C row-major)
// Tiles: 128x128x8, 256 threads, 8x8 per thread.
// ---------------------------------------------------------------------------
__global__ __launch_bounds__(256)
void sgemm_nt(const float* __restrict__ A, const float* __restrict__ B,
              float* __restrict__ C, int M, int N, int K) {
    __shared__ float As[8][128];
    __shared__ float Bs[8][128];

    const int tid = threadIdx.x;
    const int tx = tid & 15;        // 0..15 -> N direction
    const int ty = tid >> 4;        // 0..15 -> M direction
    const int lr = tid >> 1;        // 0..127 loader row
    const int lc = (tid & 1) << 2;  // 0 or 4 loader k-col (float4)

    const float* Ab = A + (size_t)(blockIdx.y * 128) * K;
    const float* Bb = B + (size_t)(blockIdx.x * 128) * K;

    float acc[8][8];
#pragma unroll
    for (int i = 0; i < 8; i++)
#pragma unroll
        for (int j = 0; j < 8; j++) acc[i][j] = 0.f;

    for (int k0 = 0; k0 < K; k0 += 8) {
        float4 av = *(const float4*)(Ab + (size_t)lr * K + k0 + lc);
        float4 bv = *(const float4*)(Bb + (size_t)lr * K + k0 + lc);
        As[lc + 0][lr] = av.x; As[lc + 1][lr] = av.y;
        As[lc + 2][lr] = av.z; As[lc + 3][lr] = av.w;
        Bs[lc + 0][lr] = bv.x; Bs[lc + 1][lr] = bv.y;
        Bs[lc + 2][lr] = bv.z; Bs[lc + 3][lr] = bv.w;
        __syncthreads();
#pragma unroll
        for (int k = 0; k < 8; k++) {
            float4 a0 = *(const float4*)&As[k][ty * 8];
            float4 a1 = *(const float4*)&As[k][ty * 8 + 4];
            float4 b0 = *(const float4*)&Bs[k][tx * 8];
            float4 b1 = *(const float4*)&Bs[k][tx * 8 + 4];
            float ar[8] = {a0.x, a0.y, a0.z, a0.w, a1.x, a1.y, a1.z, a1.w};
            float br[8] = {b0.x, b0.y, b0.z, b0.w, b1.x, b1.y, b1.z, b1.w};
#pragma unroll
            for (int i = 0; i < 8; i++)
#pragma unroll
                for (int j = 0; j < 8; j++) acc[i][j] += ar[i] * br[j];
        }
        __syncthreads();
    }

    float* Cb = C + (size_t)(blockIdx.y * 128 + ty * 8) * N + blockIdx.x * 128 + tx * 8;
#pragma unroll
    for (int i = 0; i < 8; i++) {
        float4 c0 = {acc[i][0], acc[i][1], acc[i][2], acc[i][3]};
        float4 c1 = {acc[i][4], acc[i][5], acc[i][6], acc[i][7]};
        *(float4*)(Cb + (size_t)i * N) = c0;
        *(float4*)(Cb + (size_t)i * N + 4) = c1;
    }
}

// ---------------------------------------------------------------------------
// SGEMM NN:  C[M,N] = A[M,K] * B[K,N]
// ---------------------------------------------------------------------------
__global__ __launch_bounds__(256)
void sgemm_nn(const float* __restrict__ A, const float* __restrict__ B,
              float* __restrict__ C, int M, int N, int K) {
    __shared__ float As[8][128];
    __shared__ float Bs[8][128];

    const int tid = threadIdx.x;
    const int tx = tid & 15;
    const int ty = tid >> 4;
    const int lr = tid >> 1;          // A loader: row 0..127
    const int lc = (tid & 1) << 2;    // A loader: k 0 or 4
    const int br_ = tid >> 5;         // B loader: k-row 0..7
    const int bc_ = (tid & 31) << 2;  // B loader: n-col 0..124

    const float* Ab = A + (size_t)(blockIdx.y * 128) * K;
    const float* Bb = B + blockIdx.x * 128;

    float acc[8][8];
#pragma unroll
    for (int i = 0; i < 8; i++)
#pragma unroll
        for (int j = 0; j < 8; j++) acc[i][j] = 0.f;

    for (int k0 = 0; k0 < K; k0 += 8) {
        float4 av = *(const float4*)(Ab + (size_t)lr * K + k0 + lc);
        As[lc + 0][lr] = av.x; As[lc + 1][lr] = av.y;
        As[lc + 2][lr] = av.z; As[lc + 3][lr] = av.w;
        float4 bv = *(const float4*)(Bb + (size_t)(k0 + br_) * N + bc_);
        *(float4*)&Bs[br_][bc_] = bv;
        __syncthreads();
#pragma unroll
        for (int k = 0; k < 8; k++) {
            float4 a0 = *(const float4*)&As[k][ty * 8];
            float4 a1 = *(const float4*)&As[k][ty * 8 + 4];
            float4 b0 = *(const float4*)&Bs[k][tx * 8];
            float4 b1 = *(const float4*)&Bs[k][tx * 8 + 4];
            float ar[8] = {a0.x, a0.y, a0.z, a0.w, a1.x, a1.y, a1.z, a1.w};
            float br[8] = {b0.x, b0.y, b0.z, b0.w, b1.x, b1.y, b1.z, b1.w};
#pragma unroll
            for (int i = 0; i < 8; i++)
#pragma unroll
                for (int j = 0; j < 8; j++) acc[i][j] += ar[i] * br[j];
        }
        __syncthreads();
    }

    float* Cb = C + (size_t)(blockIdx.y * 128 + ty * 8) * N + blockIdx.x * 128 + tx * 8;
#pragma unroll
    for (int i = 0; i < 8; i++) {
        float4 c0 = {acc[i][0], acc[i][1], acc[i][2], acc[i][3]};
        float4 c1 = {acc[i][4], acc[i][5], acc[i][6], acc[i][7]};
        *(float4*)(Cb + (size_t)i * N) = c0;
        *(float4*)(Cb + (size_t)i * N + 4) = c1;
    }
}

// ---------------------------------------------------------------------------
// Flash attention (fp32, causal, GQA).
// Grid: (S/64, NH, B). Block: 256 threads = 16x16; each thread owns a 4x4
// micro-tile of the 64x64 score tile and a 4x4 micro-tile of the 64x64 output.
// Shared: Qs/Ks/Vs/Ps each 64x65 floats (dynamic, ~66.5 KB).
// NOTE: 65-float stride => float4 SMEM ops on odd rows would be misaligned.
// All SMEM writes into these tiles are SCALAR stores (global side stays 128b).
// ---------------------------------------------------------------------------
#define NEG_BIG (-1e30f)

__global__ __launch_bounds__(256)
void attn_kernel(const float* __restrict__ Q, const float* __restrict__ K,
                 const float* __restrict__ V, float* __restrict__ O) {
    extern __shared__ float sm[];
    float* Qs = sm;                // [64][65]
    float* Ks = sm + 64 * 65;      // [64][65]
    float* Vs = sm + 2 * 64 * 65;  // [64][65]
    float* Ps = sm + 3 * 64 * 65;  // [64][65]

    const int qt = blockIdx.x;
    const int h  = blockIdx.y;
    const int b  = blockIdx.z;
    const int kvh = h >> 2;   // NH/NKV = 4

    const int tid = threadIdx.x;
    const int tx = tid & 15;   // k / d direction
    const int ty = tid >> 4;   // q direction

    const float* Qg = Q + ((size_t)(b * SEQ + qt * 64)) * (NH * DH) + h * DH;
    const float* Kg = K + ((size_t)b * SEQ) * (NKV * DH) + kvh * DH;
    const float* Vg = V + ((size_t)b * SEQ) * (NKV * DH) + kvh * DH;

    // load Q tile, folding in 1/sqrt(64) (scalar SMEM stores)
    for (int i = tid; i < 64 * 16; i += 256) {
        int r = i >> 4, c = (i & 15) << 2;
        float4 v = *(const float4*)(Qg + (size_t)r * (NH * DH) + c);
        Qs[r * 65 + c + 0] = v.x * 0.125f;
        Qs[r * 65 + c + 1] = v.y * 0.125f;
        Qs[r * 65 + c + 2] = v.z * 0.125f;
        Qs[r * 65 + c + 3] = v.w * 0.125f;
    }

    float m_i[4], l_i[4], acc[4][4];
#pragma unroll
    for (int i = 0; i < 4; i++) {
        m_i[i] = NEG_BIG; l_i[i] = 0.f;
#pragma unroll
        for (int j = 0; j < 4; j++) acc[i][j] = 0.f;
    }
    __syncthreads();

    for (int kt = 0; kt <= qt; kt++) {
        // load K,V tiles: 128-bit global loads, scalar SMEM stores (alignment)
        for (int i = tid; i < 64 * 16; i += 256) {
            int r = i >> 4, c = (i & 15) << 2;
            float4 kv = *(const float4*)(Kg + (size_t)(kt * 64 + r) * (NKV * DH) + c);
            float4 vv = *(const float4*)(Vg + (size_t)(kt * 64 + r) * (NKV * DH) + c);
            Ks[r * 65 + c + 0] = kv.x; Ks[r * 65 + c + 1] = kv.y;
            Ks[r * 65 + c + 2] = kv.z; Ks[r * 65 + c + 3] = kv.w;
            Vs[r * 65 + c + 0] = vv.x; Vs[r * 65 + c + 1] = vv.y;
            Vs[r * 65 + c + 2] = vv.z; Vs[r * 65 + c + 3] = vv.w;
        }
        __syncthreads();

        // scores: sc[i][j] = Qrow(ty*4+i) . Krow(tx*4+j)
        float sc[4][4];
#pragma unroll
        for (int i = 0; i < 4; i++)
#pragma unroll
            for (int j = 0; j < 4; j++) sc[i][j] = 0.f;

#pragma unroll 8
        for (int d = 0; d < 64; d++) {
            float qr[4], kr[4];
#pragma unroll
            for (int i = 0; i < 4; i++) qr[i] = Qs[(ty * 4 + i) * 65 + d];
#pragma unroll
            for (int j = 0; j < 4; j++) kr[j] = Ks[(tx * 4 + j) * 65 + d];
#pragma unroll
            for (int i = 0; i < 4; i++)
#pragma unroll
                for (int j = 0; j < 4; j++) sc[i][j] += qr[i] * kr[j];
        }

        if (kt == qt) {  // causal mask on diagonal tile
#pragma unroll
            for (int i = 0; i < 4; i++)
#pragma unroll
                for (int j = 0; j < 4; j++)
                    if (tx * 4 + j > ty * 4 + i) sc[i][j] = NEG_BIG;
        }

        // online softmax (row reductions across the 16 lanes of each row group)
#pragma unroll
        for (int i = 0; i < 4; i++) {
            float rm = fmaxf(fmaxf(sc[i][0], sc[i][1]), fmaxf(sc[i][2], sc[i][3]));
#pragma unroll
            for (int msk = 8; msk >= 1; msk >>= 1)
                rm = fmaxf(rm, __shfl_xor_sync(0xffffffffu, rm, msk));
            float mn = fmaxf(m_i[i], rm);
            float corr = __expf(m_i[i] - mn);
            float ls = 0.f;
#pragma unroll
            for (int j = 0; j < 4; j++) {
                float p = __expf(sc[i][j] - mn);
                Ps[(ty * 4 + i) * 65 + tx * 4 + j] = p;
                ls += p;
            }
#pragma unroll
            for (int msk = 8; msk >= 1; msk >>= 1)
                ls += __shfl_xor_sync(0xffffffffu, ls, msk);
            l_i[i] = l_i[i] * corr + ls;
            m_i[i] = mn;
#pragma unroll
            for (int j = 0; j < 4; j++) acc[i][j] *= corr;
        }
        __syncthreads();

        // acc += P * V
#pragma unroll 8
        for (int k = 0; k < 64; k++) {
            float pr[4], vr[4];
#pragma unroll
            for (int i = 0; i < 4; i++) pr[i] = Ps[(ty * 4 + i) * 65 + k];
#pragma unroll
            for (int j = 0; j < 4; j++) vr[j] = Vs[k * 65 + tx * 4 + j];
#pragma unroll
            for (int i = 0; i < 4; i++)
#pragma unroll
                for (int j = 0; j < 4; j++) acc[i][j] += pr[i] * vr[j];
        }
        __syncthreads();
    }

    // epilogue: normalize and store to AO [token, h*64 + d]
    float* Og = O + ((size_t)(b * SEQ + qt * 64)) * (NH * DH) + h * DH;
#pragma unroll
    for (int i = 0; i < 4; i++) {
        float inv = 1.f / l_i[i];
#pragma unroll
        for (int j = 0; j < 4; j++)
            Og[(size_t)(ty * 4 + i) * (NH * DH) + tx * 4 + j] = acc[i][j] * inv;
    }
}

// ---------------------------------------------------------------------------
// kernel_launch
// Inputs: residual, W_Q, W_K, W_V, W_O (all fp32). Output: [2,2048,2048] fp32.
// ---------------------------------------------------------------------------
extern "C" void kernel_launch(void* const* d_in, const int* in_sizes, int n_in,
                              void* d_out, int out_size) {
    const float* residual = (const float*)d_in[0];
    const float* WQ = (const float*)d_in[1];
    const float* WK = (const float*)d_in[2];
    const float* WV = (const float*)d_in[3];
    const float* WO = (const float*)d_in[4];
    float* out = (float*)d_out;

    float *Qb, *Kb, *Vb, *AOb;
    cudaGetSymbolAddress((void**)&Qb, g_Q);
    cudaGetSymbolAddress((void**)&Kb, g_K);
    cudaGetSymbolAddress((void**)&Vb, g_V);
    cudaGetSymbolAddress((void**)&AOb, g_AO);

    // QKV projections: C[t, n*64+h] = residual[t, :] . W[n*64+h, :]
    sgemm_nt<<<dim3((NH * DH) / 128, T_TOK / 128), 256>>>(
        residual, WQ, Qb, T_TOK, NH * DH, DMODEL);
    sgemm_nt<<<dim3((NKV * DH) / 128, T_TOK / 128), 256>>>(
        residual, WK, Kb, T_TOK, NKV * DH, DMODEL);
    sgemm_nt<<<dim3((NKV * DH) / 128, T_TOK / 128), 256>>>(
        residual, WV, Vb, T_TOK, NKV * DH, DMODEL);

    // flash attention
    size_t smem = (size_t)4 * 64 * 65 * sizeof(float);  // 66,560 B
    cudaFuncSetAttribute(attn_kernel, cudaFuncAttributeMaxDynamicSharedMemorySize,
                         (int)smem);
    attn_kernel<<<dim3(SEQ / 64, NH, 2), 256, smem>>>(Qb, Kb, Vb, AOb);

    // output projection: out = AO [T,2048] * W_O [2048(nh), 2048(d)]
    sgemm_nn<<<dim3(DMODEL / 128, T_TOK / 128), 256>>>(
        AOb, WO, out, T_TOK, DMODEL, DMODEL);
}

// round 4
// speedup vs baseline: 3.2606x; 3.2606x over previous
#include <cuda_runtime.h>
#include <cstdint>

// ---------------------------------------------------------------------------
// B=2, S=2048, D_MODEL=2048, N_HEADS=32, N_KV_HEADS=8, D_HEAD=64, T=4096
// ---------------------------------------------------------------------------
#define T_TOK 4096
#define DMODEL 2048
#define NH 32
#define NKV 8
#define DH 64
#define SEQ 2048

__device__ float g_Q[(size_t)T_TOK * (NH * DH)];
__device__ float g_K[(size_t)T_TOK * (NKV * DH)];
__device__ float g_V[(size_t)T_TOK * (NKV * DH)];
__device__ float g_AO[(size_t)T_TOK * (NH * DH)];

// ---------------------------------------------------------------------------
// helpers
// ---------------------------------------------------------------------------
__device__ __forceinline__ uint32_t f2tf32(float x) {
    uint32_t r;
    asm("cvt.rna.tf32.f32 %0, %1;" : "=r"(r) : "f"(x));
    return r;
}

__device__ __forceinline__ void mma_tf32(float c[4], uint32_t a0, uint32_t a1,
                                         uint32_t a2, uint32_t a3,
                                         uint32_t b0, uint32_t b1) {
    asm volatile(
        "mma.sync.aligned.m16n8k8.row.col.f32.tf32.tf32.f32 "
        "{%0,%1,%2,%3}, {%4,%5,%6,%7}, {%8,%9}, {%0,%1,%2,%3};"
        : "+f"(c[0]), "+f"(c[1]), "+f"(c[2]), "+f"(c[3])
        : "r"(a0), "r"(a1), "r"(a2), "r"(a3), "r"(b0), "r"(b1));
}

// ---------------------------------------------------------------------------
// tf32 GEMM NT: C[M,N] = A[M,K] * B[N,K]^T.  BM=BN=128, BK=32, 256 thr,
// 8 warps in 2x4, warp tile 64x32 (4x4 m16n8k8 tiles). Double-buffered SMEM.
// SMEM stride 36 (36%32==4) -> conflict-free fragment reads.
// ---------------------------------------------------------------------------
#define GLDA 36
#define ABUF (128 * GLDA)

__global__ __launch_bounds__(256)
void gemm_nt_tf32(const float* __restrict__ A, const float* __restrict__ B,
                  float* __restrict__ C, int M, int N, int K) {
    extern __shared__ uint32_t sm[];
    uint32_t* As = sm;               // [2][128*36]
    uint32_t* Bs = sm + 2 * ABUF;    // [2][128*36]

    const int tid = threadIdx.x, lane = tid & 31, wid = tid >> 5;
    const int wm = wid >> 2, wn = wid & 3;
    const int lg = lane >> 2, lt = lane & 3;

    const float* Ab = A + (size_t)(blockIdx.y * 128) * K;
    const float* Bb = B + (size_t)(blockIdx.x * 128) * K;

    float acc[4][4][4];
#pragma unroll
    for (int i = 0; i < 4; i++)
#pragma unroll
        for (int j = 0; j < 4; j++)
#pragma unroll
            for (int r = 0; r < 4; r++) acc[i][j][r] = 0.f;

    float4 pa[4], pb[4];
#define GLOAD(k0)                                                        \
    {                                                                    \
        _Pragma("unroll") for (int i = 0; i < 4; i++) {                  \
            int idx = tid + i * 256;                                     \
            pa[i] = *(const float4*)(Ab + (size_t)(idx >> 3) * K + (k0) + (idx & 7) * 4); \
            pb[i] = *(const float4*)(Bb + (size_t)(idx >> 3) * K + (k0) + (idx & 7) * 4); \
        }                                                                \
    }
#define SSTORE(buf)                                                      \
    {                                                                    \
        _Pragma("unroll") for (int i = 0; i < 4; i++) {                  \
            int idx = tid + i * 256;                                     \
            uint32_t* pA = &As[(buf)*ABUF + (idx >> 3) * GLDA + (idx & 7) * 4]; \
            pA[0] = f2tf32(pa[i].x); pA[1] = f2tf32(pa[i].y);            \
            pA[2] = f2tf32(pa[i].z); pA[3] = f2tf32(pa[i].w);            \
            uint32_t* pB = &Bs[(buf)*ABUF + (idx >> 3) * GLDA + (idx & 7) * 4]; \
            pB[0] = f2tf32(pb[i].x); pB[1] = f2tf32(pb[i].y);            \
            pB[2] = f2tf32(pb[i].z); pB[3] = f2tf32(pb[i].w);            \
        }                                                                \
    }

    GLOAD(0); SSTORE(0);
    __syncthreads();

    const int nsteps = K / 32;
    for (int t = 0; t < nsteps; t++) {
        if (t + 1 < nsteps) GLOAD((t + 1) * 32);
        const uint32_t* Acur = &As[(t & 1) * ABUF];
        const uint32_t* Bcur = &Bs[(t & 1) * ABUF];
#pragma unroll
        for (int ks = 0; ks < 4; ks++) {
            uint32_t af[4][4];
#pragma unroll
            for (int mi = 0; mi < 4; mi++) {
                int r = wm * 64 + mi * 16 + lg, c = ks * 8 + lt;
                af[mi][0] = Acur[r * GLDA + c];
                af[mi][1] = Acur[(r + 8) * GLDA + c];
                af[mi][2] = Acur[r * GLDA + c + 4];
                af[mi][3] = Acur[(r + 8) * GLDA + c + 4];
            }
#pragma unroll
            for (int ni = 0; ni < 4; ni++) {
                int cb = wn * 32 + ni * 8 + lg, ck = ks * 8 + lt;
                uint32_t b0 = Bcur[cb * GLDA + ck];
                uint32_t b1 = Bcur[cb * GLDA + ck + 4];
#pragma unroll
                for (int mi = 0; mi < 4; mi++)
                    mma_tf32(acc[mi][ni], af[mi][0], af[mi][1], af[mi][2], af[mi][3], b0, b1);
            }
        }
        if (t + 1 < nsteps) SSTORE((t + 1) & 1);
        __syncthreads();
    }

#pragma unroll
    for (int mi = 0; mi < 4; mi++) {
        int row = blockIdx.y * 128 + wm * 64 + mi * 16 + lg;
#pragma unroll
        for (int ni = 0; ni < 4; ni++) {
            int col = blockIdx.x * 128 + wn * 32 + ni * 8 + lt * 2;
            *(float2*)(C + (size_t)row * N + col) = make_float2(acc[mi][ni][0], acc[mi][ni][1]);
            *(float2*)(C + (size_t)(row + 8) * N + col) = make_float2(acc[mi][ni][2], acc[mi][ni][3]);
        }
    }
#undef GLOAD
#undef SSTORE
}

// ---------------------------------------------------------------------------
// tf32 GEMM NN: C[M,N] = A[M,K] * B[K,N].  B tile kept row-major [32][132].
// ---------------------------------------------------------------------------
#define GLDB 132
#define BBUF (32 * GLDB)

__global__ __launch_bounds__(256)
void gemm_nn_tf32(const float* __restrict__ A, const float* __restrict__ B,
                  float* __restrict__ C, int M, int N, int K) {
    extern __shared__ uint32_t sm[];
    uint32_t* As = sm;               // [2][128*36]
    uint32_t* Bs = sm + 2 * ABUF;    // [2][32*132]

    const int tid = threadIdx.x, lane = tid & 31, wid = tid >> 5;
    const int wm = wid >> 2, wn = wid & 3;
    const int lg = lane >> 2, lt = lane & 3;

    const float* Ab = A + (size_t)(blockIdx.y * 128) * K;
    const float* Bb = B + blockIdx.x * 128;

    float acc[4][4][4];
#pragma unroll
    for (int i = 0; i < 4; i++)
#pragma unroll
        for (int j = 0; j < 4; j++)
#pragma unroll
            for (int r = 0; r < 4; r++) acc[i][j][r] = 0.f;

    float4 pa[4], pb[4];
#define GLOAD(k0)                                                        \
    {                                                                    \
        _Pragma("unroll") for (int i = 0; i < 4; i++) {                  \
            int idx = tid + i * 256;                                     \
            pa[i] = *(const float4*)(Ab + (size_t)(idx >> 3) * K + (k0) + (idx & 7) * 4); \
            pb[i] = *(const float4*)(Bb + (size_t)((k0) + (idx >> 5)) * N + (idx & 31) * 4); \
        }                                                                \
    }
#define SSTORE(buf)                                                      \
    {                                                                    \
        _Pragma("unroll") for (int i = 0; i < 4; i++) {                  \
            int idx = tid + i * 256;                                     \
            uint32_t* pA = &As[(buf)*ABUF + (idx >> 3) * GLDA + (idx & 7) * 4]; \
            pA[0] = f2tf32(pa[i].x); pA[1] = f2tf32(pa[i].y);            \
            pA[2] = f2tf32(pa[i].z); pA[3] = f2tf32(pa[i].w);            \
            uint32_t* pB = &Bs[(buf)*BBUF + (idx >> 5) * GLDB + (idx & 31) * 4]; \
            pB[0] = f2tf32(pb[i].x); pB[1] = f2tf32(pb[i].y);            \
            pB[2] = f2tf32(pb[i].z); pB[3] = f2tf32(pb[i].w);            \
        }                                                                \
    }

    GLOAD(0); SSTORE(0);
    __syncthreads();

    const int nsteps = K / 32;
    for (int t = 0; t < nsteps; t++) {
        if (t + 1 < nsteps) GLOAD((t + 1) * 32);
        const uint32_t* Acur = &As[(t & 1) * ABUF];
        const uint32_t* Bcur = &Bs[(t & 1) * BBUF];
#pragma unroll
        for (int ks = 0; ks < 4; ks++) {
            uint32_t af[4][4];
#pragma unroll
            for (int mi = 0; mi < 4; mi++) {
                int r = wm * 64 + mi * 16 + lg, c = ks * 8 + lt;
                af[mi][0] = Acur[r * GLDA + c];
                af[mi][1] = Acur[(r + 8) * GLDA + c];
                af[mi][2] = Acur[r * GLDA + c + 4];
                af[mi][3] = Acur[(r + 8) * GLDA + c + 4];
            }
#pragma unroll
            for (int ni = 0; ni < 4; ni++) {
                int cn = wn * 32 + ni * 8 + lg;
                uint32_t b0 = Bcur[(ks * 8 + lt) * GLDB + cn];
                uint32_t b1 = Bcur[(ks * 8 + lt + 4) * GLDB + cn];
#pragma unroll
                for (int mi = 0; mi < 4; mi++)
                    mma_tf32(acc[mi][ni], af[mi][0], af[mi][1], af[mi][2], af[mi][3], b0, b1);
            }
        }
        if (t + 1 < nsteps) SSTORE((t + 1) & 1);
        __syncthreads();
    }

#pragma unroll
    for (int mi = 0; mi < 4; mi++) {
        int row = blockIdx.y * 128 + wm * 64 + mi * 16 + lg;
#pragma unroll
        for (int ni = 0; ni < 4; ni++) {
            int col = blockIdx.x * 128 + wn * 32 + ni * 8 + lt * 2;
            *(float2*)(C + (size_t)row * N + col) = make_float2(acc[mi][ni][0], acc[mi][ni][1]);
            *(float2*)(C + (size_t)(row + 8) * N + col) = make_float2(acc[mi][ni][2], acc[mi][ni][3]);
        }
    }
#undef GLOAD
#undef SSTORE
}

// ---------------------------------------------------------------------------
// Flash attention, tf32 tensor cores. Block: 128 thr (4 warps), Q tile 64.
// Warp w owns q-rows [w*16, w*16+16). Grid (S/64, NH, B).
// SMEM (tf32 bits): Qs/Ks/Vs/Ps [64][68] each (stride 68 -> 68%32==4).
// ---------------------------------------------------------------------------
#define ALDS 68
#define ATS (64 * ALDS)
#define NEG_BIG (-1e30f)

__global__ __launch_bounds__(128)
void attn_tf32(const float* __restrict__ Q, const float* __restrict__ K,
               const float* __restrict__ V, float* __restrict__ O) {
    extern __shared__ uint32_t sm[];
    uint32_t* Qs = sm;
    uint32_t* Ks = sm + ATS;
    uint32_t* Vs = sm + 2 * ATS;
    uint32_t* Ps = sm + 3 * ATS;

    const int qt = blockIdx.x, h = blockIdx.y, b = blockIdx.z;
    const int kvh = h >> 2;
    const int tid = threadIdx.x, lane = tid & 31, wid = tid >> 5;
    const int lg = lane >> 2, lt = lane & 3;
    const int q0 = wid * 16;

    const float* Qg = Q + ((size_t)(b * SEQ + qt * 64)) * (NH * DH) + h * DH;
    const float* Kg = K + ((size_t)b * SEQ) * (NKV * DH) + kvh * DH;
    const float* Vg = V + ((size_t)b * SEQ) * (NKV * DH) + kvh * DH;

    // Q tile (scaled by 1/8)
#pragma unroll
    for (int i = 0; i < 8; i++) {
        int idx = tid + i * 128;
        int r = idx >> 4, c = (idx & 15) * 4;
        float4 v = *(const float4*)(Qg + (size_t)r * (NH * DH) + c);
        Qs[r * ALDS + c + 0] = f2tf32(v.x * 0.125f);
        Qs[r * ALDS + c + 1] = f2tf32(v.y * 0.125f);
        Qs[r * ALDS + c + 2] = f2tf32(v.z * 0.125f);
        Qs[r * ALDS + c + 3] = f2tf32(v.w * 0.125f);
    }

    float m0 = NEG_BIG, m1 = NEG_BIG, l0 = 0.f, l1 = 0.f;
    float acc[8][4];
#pragma unroll
    for (int d = 0; d < 8; d++)
#pragma unroll
        for (int r = 0; r < 4; r++) acc[d][r] = 0.f;
    __syncthreads();

    for (int kt = 0; kt <= qt; kt++) {
#pragma unroll
        for (int i = 0; i < 8; i++) {
            int idx = tid + i * 128;
            int r = idx >> 4, c = (idx & 15) * 4;
            const float* kp = Kg + (size_t)(kt * 64 + r) * (NKV * DH) + c;
            const float* vp = Vg + (size_t)(kt * 64 + r) * (NKV * DH) + c;
            float4 kv = *(const float4*)kp;
            float4 vv = *(const float4*)vp;
            Ks[r * ALDS + c + 0] = f2tf32(kv.x); Ks[r * ALDS + c + 1] = f2tf32(kv.y);
            Ks[r * ALDS + c + 2] = f2tf32(kv.z); Ks[r * ALDS + c + 3] = f2tf32(kv.w);
            Vs[r * ALDS + c + 0] = f2tf32(vv.x); Vs[r * ALDS + c + 1] = f2tf32(vv.y);
            Vs[r * ALDS + c + 2] = f2tf32(vv.z); Vs[r * ALDS + c + 3] = f2tf32(vv.w);
        }
        __syncthreads();

        // scores = Q Kt : 8 n-tiles of m16n8, k=64
        float sc[8][4];
#pragma unroll
        for (int ni = 0; ni < 8; ni++)
#pragma unroll
            for (int r = 0; r < 4; r++) sc[ni][r] = 0.f;
#pragma unroll
        for (int ks = 0; ks < 8; ks++) {
            int rA = q0 + lg, cA = ks * 8 + lt;
            uint32_t a0 = Qs[rA * ALDS + cA];
            uint32_t a1 = Qs[(rA + 8) * ALDS + cA];
            uint32_t a2 = Qs[rA * ALDS + cA + 4];
            uint32_t a3 = Qs[(rA + 8) * ALDS + cA + 4];
#pragma unroll
            for (int ni = 0; ni < 8; ni++) {
                int rB = ni * 8 + lg, cB = ks * 8 + lt;
                uint32_t b0 = Ks[rB * ALDS + cB];
                uint32_t b1 = Ks[rB * ALDS + cB + 4];
                mma_tf32(sc[ni], a0, a1, a2, a3, b0, b1);
            }
        }

        if (kt == qt) {  // causal mask on diagonal tile
            int r0 = q0 + lg, r1 = r0 + 8;
#pragma unroll
            for (int ni = 0; ni < 8; ni++) {
                int c = ni * 8 + lt * 2;
                if (c > r0) sc[ni][0] = NEG_BIG;
                if (c + 1 > r0) sc[ni][1] = NEG_BIG;
                if (c > r1) sc[ni][2] = NEG_BIG;
                if (c + 1 > r1) sc[ni][3] = NEG_BIG;
            }
        }

        // online softmax: thread handles rows (q0+lg) and (q0+lg+8)
        float mx0 = NEG_BIG, mx1 = NEG_BIG;
#pragma unroll
        for (int ni = 0; ni < 8; ni++) {
            mx0 = fmaxf(mx0, fmaxf(sc[ni][0], sc[ni][1]));
            mx1 = fmaxf(mx1, fmaxf(sc[ni][2], sc[ni][3]));
        }
        mx0 = fmaxf(mx0, __shfl_xor_sync(0xffffffffu, mx0, 1));
        mx0 = fmaxf(mx0, __shfl_xor_sync(0xffffffffu, mx0, 2));
        mx1 = fmaxf(mx1, __shfl_xor_sync(0xffffffffu, mx1, 1));
        mx1 = fmaxf(mx1, __shfl_xor_sync(0xffffffffu, mx1, 2));
        float nm0 = fmaxf(m0, mx0), nm1 = fmaxf(m1, mx1);
        float corr0 = __expf(m0 - nm0), corr1 = __expf(m1 - nm1);
        m0 = nm0; m1 = nm1;

        float s0 = 0.f, s1 = 0.f;
        int pr0 = (q0 + lg) * ALDS, pr1 = (q0 + lg + 8) * ALDS;
#pragma unroll
        for (int ni = 0; ni < 8; ni++) {
            int c = ni * 8 + lt * 2;
            float p00 = __expf(sc[ni][0] - m0), p01 = __expf(sc[ni][1] - m0);
            float p10 = __expf(sc[ni][2] - m1), p11 = __expf(sc[ni][3] - m1);
            s0 += p00 + p01; s1 += p10 + p11;
            Ps[pr0 + c] = f2tf32(p00); Ps[pr0 + c + 1] = f2tf32(p01);
            Ps[pr1 + c] = f2tf32(p10); Ps[pr1 + c + 1] = f2tf32(p11);
        }
        s0 += __shfl_xor_sync(0xffffffffu, s0, 1);
        s0 += __shfl_xor_sync(0xffffffffu, s0, 2);
        s1 += __shfl_xor_sync(0xffffffffu, s1, 1);
        s1 += __shfl_xor_sync(0xffffffffu, s1, 2);
        l0 = l0 * corr0 + s0;
        l1 = l1 * corr1 + s1;
#pragma unroll
        for (int d = 0; d < 8; d++) {
            acc[d][0] *= corr0; acc[d][1] *= corr0;
            acc[d][2] *= corr1; acc[d][3] *= corr1;
        }
        __syncwarp();

        // acc += P V : 8 d-tiles, k=64
#pragma unroll
        for (int ks = 0; ks < 8; ks++) {
            int rA = q0 + lg, cA = ks * 8 + lt;
            uint32_t a0 = Ps[rA * ALDS + cA];
            uint32_t a1 = Ps[(rA + 8) * ALDS + cA];
            uint32_t a2 = Ps[rA * ALDS + cA + 4];
            uint32_t a3 = Ps[(rA + 8) * ALDS + cA + 4];
#pragma unroll
            for (int di = 0; di < 8; di++) {
                int cn = di * 8 + lg;
                uint32_t b0 = Vs[(ks * 8 + lt) * ALDS + cn];
                uint32_t b1 = Vs[(ks * 8 + lt + 4) * ALDS + cn];
                mma_tf32(acc[di], a0, a1, a2, a3, b0, b1);
            }
        }
        __syncthreads();
    }

    // epilogue
    float inv0 = 1.f / l0, inv1 = 1.f / l1;
    float* Og = O + ((size_t)(b * SEQ + qt * 64 + q0 + lg)) * (NH * DH) + h * DH;
#pragma unroll
    for (int di = 0; di < 8; di++) {
        int c = di * 8 + lt * 2;
        *(float2*)(Og + c) = make_float2(acc[di][0] * inv0, acc[di][1] * inv0);
        *(float2*)(Og + (size_t)8 * (NH * DH) + c) = make_float2(acc[di][2] * inv1, acc[di][3] * inv1);
    }
}

// ---------------------------------------------------------------------------
// kernel_launch
// ---------------------------------------------------------------------------
extern "C" void kernel_launch(void* const* d_in, const int* in_sizes, int n_in,
                              void* d_out, int out_size) {
    const float* residual = (const float*)d_in[0];
    const float* WQ = (const float*)d_in[1];
    const float* WK = (const float*)d_in[2];
    const float* WV = (const float*)d_in[3];
    const float* WO = (const float*)d_in[4];
    float* out = (float*)d_out;

    float *Qb, *Kb, *Vb, *AOb;
    cudaGetSymbolAddress((void**)&Qb, g_Q);
    cudaGetSymbolAddress((void**)&Kb, g_K);
    cudaGetSymbolAddress((void**)&Vb, g_V);
    cudaGetSymbolAddress((void**)&AOb, g_AO);

    static int attrs_set = 0;
    size_t smem_nt = (size_t)4 * ABUF * 4;            // 2 bufs A + 2 bufs B
    size_t smem_nn = ((size_t)2 * ABUF + 2 * BBUF) * 4;
    size_t smem_at = (size_t)4 * ATS * 4;
    if (!attrs_set) {
        cudaFuncSetAttribute(gemm_nt_tf32, cudaFuncAttributeMaxDynamicSharedMemorySize, (int)smem_nt);
        cudaFuncSetAttribute(gemm_nn_tf32, cudaFuncAttributeMaxDynamicSharedMemorySize, (int)smem_nn);
        cudaFuncSetAttribute(attn_tf32, cudaFuncAttributeMaxDynamicSharedMemorySize, (int)smem_at);
        attrs_set = 1;
    }

    gemm_nt_tf32<<<dim3((NH * DH) / 128, T_TOK / 128), 256, smem_nt>>>(
        residual, WQ, Qb, T_TOK, NH * DH, DMODEL);
    gemm_nt_tf32<<<dim3((NKV * DH) / 128, T_TOK / 128), 256, smem_nt>>>(
        residual, WK, Kb, T_TOK, NKV * DH, DMODEL);
    gemm_nt_tf32<<<dim3((NKV * DH) / 128, T_TOK / 128), 256, smem_nt>>>(
        residual, WV, Vb, T_TOK, NKV * DH, DMODEL);

    attn_tf32<<<dim3(SEQ / 64, NH, 2), 128, smem_at>>>(Qb, Kb, Vb, AOb);

    gemm_nn_tf32<<<dim3(DMODEL / 128, T_TOK / 128), 256, smem_nn>>>(
        AOb, WO, out, T_TOK, DMODEL, DMODEL);
}

// round 6
// speedup vs baseline: 3.3736x; 1.0347x over previous
#include <cuda_runtime.h>
#include <cstdint>

// ---------------------------------------------------------------------------
// B=2, S=2048, D_MODEL=2048, N_HEADS=32, N_KV_HEADS=8, D_HEAD=64, T=4096
// ---------------------------------------------------------------------------
#define T_TOK 4096
#define DMODEL 2048
#define NH 32
#define NKV 8
#define DH 64
#define SEQ 2048

__device__ float g_Q[(size_t)T_TOK * (NH * DH)];
__device__ float g_K[(size_t)T_TOK * (NKV * DH)];
__device__ float g_V[(size_t)T_TOK * (NKV * DH)];
__device__ float g_AO[(size_t)T_TOK * (NH * DH)];

// ---------------------------------------------------------------------------
// helpers
// ---------------------------------------------------------------------------
__device__ __forceinline__ uint32_t f2tf32(float x) {
    uint32_t r;
    asm("cvt.rna.tf32.f32 %0, %1;" : "=r"(r) : "f"(x));
    return r;
}

__device__ __forceinline__ void mma_tf32(float c[4], uint32_t a0, uint32_t a1,
                                         uint32_t a2, uint32_t a3,
                                         uint32_t b0, uint32_t b1) {
    asm volatile(
        "mma.sync.aligned.m16n8k8.row.col.f32.tf32.tf32.f32 "
        "{%0,%1,%2,%3}, {%4,%5,%6,%7}, {%8,%9}, {%0,%1,%2,%3};"
        : "+f"(c[0]), "+f"(c[1]), "+f"(c[2]), "+f"(c[3])
        : "r"(a0), "r"(a1), "r"(a2), "r"(a3), "r"(b0), "r"(b1));
}

// ---------------------------------------------------------------------------
// Fused QKV tf32 GEMM (NT): C[M,Nx] = A[M,2048] * Wx[Nx,2048]^T
// blockIdx.x 0..15 -> W_Q (N=2048), 16..19 -> W_K, 20..23 -> W_V (N=512).
// BM=BN=128, BK=32, 256 thr, 8 warps 2x4, warp tile 64x32. Double-buffered.
// SMEM row stride 36 words (144B: 16B-aligned rows, 36%32==4 conflict-free).
// ---------------------------------------------------------------------------
#define GLDA 36
#define ABUF (128 * GLDA)

__global__ __launch_bounds__(256)
void gemm_qkv_tf32(const float* __restrict__ A,
                   const float* __restrict__ WQ, const float* __restrict__ WK,
                   const float* __restrict__ WV,
                   float* __restrict__ Qo, float* __restrict__ Ko,
                   float* __restrict__ Vo) {
    extern __shared__ uint32_t sm[];
    uint32_t* As = sm;
    uint32_t* Bs = sm + 2 * ABUF;

    const int bx = blockIdx.x;
    const float* Bmat;
    float* C;
    int N, cb0;
    if (bx < 16)      { Bmat = WQ; C = Qo; N = 2048; cb0 = bx; }
    else if (bx < 20) { Bmat = WK; C = Ko; N = 512;  cb0 = bx - 16; }
    else              { Bmat = WV; C = Vo; N = 512;  cb0 = bx - 20; }

    const int Kd = DMODEL;
    const int tid = threadIdx.x, lane = tid & 31, wid = tid >> 5;
    const int wm = wid >> 2, wn = wid & 3;
    const int lg = lane >> 2, lt = lane & 3;

    const float* Ab = A + (size_t)(blockIdx.y * 128) * Kd;
    const float* Bb = Bmat + (size_t)cb0 * 128 * Kd;

    float acc[4][4][4];
#pragma unroll
    for (int i = 0; i < 4; i++)
#pragma unroll
        for (int j = 0; j < 4; j++)
#pragma unroll
            for (int r = 0; r < 4; r++) acc[i][j][r] = 0.f;

    float4 pa[4], pb[4];
#define GLOAD(k0)                                                               \
    {                                                                           \
        _Pragma("unroll") for (int i = 0; i < 4; i++) {                         \
            int idx = tid + i * 256;                                            \
            pa[i] = *(const float4*)(Ab + (size_t)(idx >> 3) * Kd + (k0) + (idx & 7) * 4); \
            pb[i] = *(const float4*)(Bb + (size_t)(idx >> 3) * Kd + (k0) + (idx & 7) * 4); \
        }                                                                       \
    }
#define SSTORE(buf)                                                             \
    {                                                                           \
        _Pragma("unroll") for (int i = 0; i < 4; i++) {                         \
            int idx = tid + i * 256;                                            \
            uint4 qa = {f2tf32(pa[i].x), f2tf32(pa[i].y), f2tf32(pa[i].z), f2tf32(pa[i].w)}; \
            *(uint4*)&As[(buf)*ABUF + (idx >> 3) * GLDA + (idx & 7) * 4] = qa;  \
            uint4 qb = {f2tf32(pb[i].x), f2tf32(pb[i].y), f2tf32(pb[i].z), f2tf32(pb[i].w)}; \
            *(uint4*)&Bs[(buf)*ABUF + (idx >> 3) * GLDA + (idx & 7) * 4] = qb;  \
        }                                                                       \
    }

    GLOAD(0); SSTORE(0);
    __syncthreads();

    const int nsteps = Kd / 32;
    for (int t = 0; t < nsteps; t++) {
        if (t + 1 < nsteps) GLOAD((t + 1) * 32);
        const uint32_t* Acur = &As[(t & 1) * ABUF];
        const uint32_t* Bcur = &Bs[(t & 1) * ABUF];
#pragma unroll
        for (int ks = 0; ks < 4; ks++) {
            uint32_t af[4][4];
#pragma unroll
            for (int mi = 0; mi < 4; mi++) {
                int r = wm * 64 + mi * 16 + lg, c = ks * 8 + lt;
                af[mi][0] = Acur[r * GLDA + c];
                af[mi][1] = Acur[(r + 8) * GLDA + c];
                af[mi][2] = Acur[r * GLDA + c + 4];
                af[mi][3] = Acur[(r + 8) * GLDA + c + 4];
            }
#pragma unroll
            for (int ni = 0; ni < 4; ni++) {
                int cb = wn * 32 + ni * 8 + lg, ck = ks * 8 + lt;
                uint32_t b0 = Bcur[cb * GLDA + ck];
                uint32_t b1 = Bcur[cb * GLDA + ck + 4];
#pragma unroll
                for (int mi = 0; mi < 4; mi++)
                    mma_tf32(acc[mi][ni], af[mi][0], af[mi][1], af[mi][2], af[mi][3], b0, b1);
            }
        }
        if (t + 1 < nsteps) SSTORE((t + 1) & 1);
        __syncthreads();
    }

#pragma unroll
    for (int mi = 0; mi < 4; mi++) {
        int row = blockIdx.y * 128 + wm * 64 + mi * 16 + lg;
#pragma unroll
        for (int ni = 0; ni < 4; ni++) {
            int col = cb0 * 128 + wn * 32 + ni * 8 + lt * 2;
            *(float2*)(C + (size_t)row * N + col) = make_float2(acc[mi][ni][0], acc[mi][ni][1]);
            *(float2*)(C + (size_t)(row + 8) * N + col) = make_float2(acc[mi][ni][2], acc[mi][ni][3]);
        }
    }
#undef GLOAD
#undef SSTORE
}

// ---------------------------------------------------------------------------
// tf32 GEMM NN: C[M,N] = A[M,K] * B[K,N].  B tile row-major [32][132].
// ---------------------------------------------------------------------------
#define GLDB 132
#define BBUF (32 * GLDB)

__global__ __launch_bounds__(256)
void gemm_nn_tf32(const float* __restrict__ A, const float* __restrict__ B,
                  float* __restrict__ C, int M, int N, int K) {
    extern __shared__ uint32_t sm[];
    uint32_t* As = sm;
    uint32_t* Bs = sm + 2 * ABUF;

    const int tid = threadIdx.x, lane = tid & 31, wid = tid >> 5;
    const int wm = wid >> 2, wn = wid & 3;
    const int lg = lane >> 2, lt = lane & 3;

    const float* Ab = A + (size_t)(blockIdx.y * 128) * K;
    const float* Bb = B + blockIdx.x * 128;

    float acc[4][4][4];
#pragma unroll
    for (int i = 0; i < 4; i++)
#pragma unroll
        for (int j = 0; j < 4; j++)
#pragma unroll
            for (int r = 0; r < 4; r++) acc[i][j][r] = 0.f;

    float4 pa[4], pb[4];
#define GLOAD(k0)                                                               \
    {                                                                           \
        _Pragma("unroll") for (int i = 0; i < 4; i++) {                         \
            int idx = tid + i * 256;                                            \
            pa[i] = *(const float4*)(Ab + (size_t)(idx >> 3) * K + (k0) + (idx & 7) * 4); \
            pb[i] = *(const float4*)(Bb + (size_t)((k0) + (idx >> 5)) * N + (idx & 31) * 4); \
        }                                                                       \
    }
#define SSTORE(buf)                                                             \
    {                                                                           \
        _Pragma("unroll") for (int i = 0; i < 4; i++) {                         \
            int idx = tid + i * 256;                                            \
            uint4 qa = {f2tf32(pa[i].x), f2tf32(pa[i].y), f2tf32(pa[i].z), f2tf32(pa[i].w)}; \
            *(uint4*)&As[(buf)*ABUF + (idx >> 3) * GLDA + (idx & 7) * 4] = qa;  \
            uint4 qb = {f2tf32(pb[i].x), f2tf32(pb[i].y), f2tf32(pb[i].z), f2tf32(pb[i].w)}; \
            *(uint4*)&Bs[(buf)*BBUF + (idx >> 5) * GLDB + (idx & 31) * 4] = qb;  \
        }                                                                       \
    }

    GLOAD(0); SSTORE(0);
    __syncthreads();

    const int nsteps = K / 32;
    for (int t = 0; t < nsteps; t++) {
        if (t + 1 < nsteps) GLOAD((t + 1) * 32);
        const uint32_t* Acur = &As[(t & 1) * ABUF];
        const uint32_t* Bcur = &Bs[(t & 1) * BBUF];
#pragma unroll
        for (int ks = 0; ks < 4; ks++) {
            uint32_t af[4][4];
#pragma unroll
            for (int mi = 0; mi < 4; mi++) {
                int r = wm * 64 + mi * 16 + lg, c = ks * 8 + lt;
                af[mi][0] = Acur[r * GLDA + c];
                af[mi][1] = Acur[(r + 8) * GLDA + c];
                af[mi][2] = Acur[r * GLDA + c + 4];
                af[mi][3] = Acur[(r + 8) * GLDA + c + 4];
            }
#pragma unroll
            for (int ni = 0; ni < 4; ni++) {
                int cn = wn * 32 + ni * 8 + lg;
                uint32_t b0 = Bcur[(ks * 8 + lt) * GLDB + cn];
                uint32_t b1 = Bcur[(ks * 8 + lt + 4) * GLDB + cn];
#pragma unroll
                for (int mi = 0; mi < 4; mi++)
                    mma_tf32(acc[mi][ni], af[mi][0], af[mi][1], af[mi][2], af[mi][3], b0, b1);
            }
        }
        if (t + 1 < nsteps) SSTORE((t + 1) & 1);
        __syncthreads();
    }

#pragma unroll
    for (int mi = 0; mi < 4; mi++) {
        int row = blockIdx.y * 128 + wm * 64 + mi * 16 + lg;
#pragma unroll
        for (int ni = 0; ni < 4; ni++) {
            int col = blockIdx.x * 128 + wn * 32 + ni * 8 + lt * 2;
            *(float2*)(C + (size_t)row * N + col) = make_float2(acc[mi][ni][0], acc[mi][ni][1]);
            *(float2*)(C + (size_t)(row + 8) * N + col) = make_float2(acc[mi][ni][2], acc[mi][ni][3]);
        }
    }
#undef GLOAD
#undef SSTORE
}

// ---------------------------------------------------------------------------
// Flash attention, tf32, BM=128 Q rows, K tile 64. Block: 256 thr (8 warps),
// warp w owns q-rows [w*16, w*16+16). Grid (S/128, NH, B).
// SMEM words: Qs[128][68] Ks[64][68] Vs[64][68] Ps[128][68]  (~102 KB)
// Stride 68 -> rows 16B-aligned (272B), 68%32==4 conflict-free frag reads.
// Warps skip K tiles that are fully causally masked for their rows
// (P rows are warp-private, so no cross-warp dependency).
// ---------------------------------------------------------------------------
#define ALDS 68
#define NEG_BIG (-1e30f)

__global__ __launch_bounds__(256)
void attn_tf32(const float* __restrict__ Q, const float* __restrict__ K,
               const float* __restrict__ V, float* __restrict__ O) {
    extern __shared__ uint32_t sm[];
    uint32_t* Qs = sm;                    // 128 rows
    uint32_t* Ks = sm + 128 * ALDS;       // 64 rows
    uint32_t* Vs = sm + 192 * ALDS;       // 64 rows
    uint32_t* Ps = sm + 256 * ALDS;       // 128 rows

    const int qt = blockIdx.x, h = blockIdx.y, b = blockIdx.z;
    const int kvh = h >> 2;
    const int tid = threadIdx.x, lane = tid & 31, wid = tid >> 5;
    const int lg = lane >> 2, lt = lane & 3;
    const int q0 = wid * 16;              // warp's first q row in tile

    const float* Qg = Q + ((size_t)(b * SEQ + qt * 128)) * (NH * DH) + h * DH;
    const float* Kg = K + ((size_t)b * SEQ) * (NKV * DH) + kvh * DH;
    const float* Vg = V + ((size_t)b * SEQ) * (NKV * DH) + kvh * DH;

    // Q tile: 128x64, scaled by 1/8, vectorized STS
#pragma unroll
    for (int i = 0; i < 8; i++) {
        int idx = tid + i * 256;
        int r = idx >> 4, c = (idx & 15) * 4;
        float4 v = *(const float4*)(Qg + (size_t)r * (NH * DH) + c);
        uint4 qv = {f2tf32(v.x * 0.125f), f2tf32(v.y * 0.125f),
                    f2tf32(v.z * 0.125f), f2tf32(v.w * 0.125f)};
        *(uint4*)&Qs[r * ALDS + c] = qv;
    }

    float m0 = NEG_BIG, m1 = NEG_BIG, l0 = 0.f, l1 = 0.f;
    float acc[8][4];
#pragma unroll
    for (int d = 0; d < 8; d++)
#pragma unroll
        for (int r = 0; r < 4; r++) acc[d][r] = 0.f;

    const int ktmax = 2 * qt + 1;         // last K tile index (inclusive)
    const int warp_qlast = qt * 128 + q0 + 15;

    for (int kt = 0; kt <= ktmax; kt++) {
        // K,V tiles 64x64, vectorized
#pragma unroll
        for (int i = 0; i < 4; i++) {
            int idx = tid + i * 256;
            int r = idx >> 4, c = (idx & 15) * 4;
            float4 kv = *(const float4*)(Kg + (size_t)(kt * 64 + r) * (NKV * DH) + c);
            float4 vv = *(const float4*)(Vg + (size_t)(kt * 64 + r) * (NKV * DH) + c);
            uint4 ku = {f2tf32(kv.x), f2tf32(kv.y), f2tf32(kv.z), f2tf32(kv.w)};
            uint4 vu = {f2tf32(vv.x), f2tf32(vv.y), f2tf32(vv.z), f2tf32(vv.w)};
            *(uint4*)&Ks[r * ALDS + c] = ku;
            *(uint4*)&Vs[r * ALDS + c] = vu;
        }
        __syncthreads();

        if (kt * 64 <= warp_qlast) {      // tile not fully masked for this warp
            // scores = Q K^T : 8 n-tiles m16n8, k=64
            float sc[8][4];
#pragma unroll
            for (int ni = 0; ni < 8; ni++)
#pragma unroll
                for (int r = 0; r < 4; r++) sc[ni][r] = 0.f;
#pragma unroll
            for (int ks = 0; ks < 8; ks++) {
                int rA = q0 + lg, cA = ks * 8 + lt;
                uint32_t a0 = Qs[rA * ALDS + cA];
                uint32_t a1 = Qs[(rA + 8) * ALDS + cA];
                uint32_t a2 = Qs[rA * ALDS + cA + 4];
                uint32_t a3 = Qs[(rA + 8) * ALDS + cA + 4];
#pragma unroll
                for (int ni = 0; ni < 8; ni++) {
                    int rB = ni * 8 + lg, cB = ks * 8 + lt;
                    uint32_t b0 = Ks[rB * ALDS + cB];
                    uint32_t b1 = Ks[rB * ALDS + cB + 4];
                    mma_tf32(sc[ni], a0, a1, a2, a3, b0, b1);
                }
            }

            if (kt * 64 + 63 > qt * 128 + q0) {  // diagonal region: mask
                int r0g = qt * 128 + q0 + lg, r1g = r0g + 8;
#pragma unroll
                for (int ni = 0; ni < 8; ni++) {
                    int cg = kt * 64 + ni * 8 + lt * 2;
                    if (cg > r0g) sc[ni][0] = NEG_BIG;
                    if (cg + 1 > r0g) sc[ni][1] = NEG_BIG;
                    if (cg > r1g) sc[ni][2] = NEG_BIG;
                    if (cg + 1 > r1g) sc[ni][3] = NEG_BIG;
                }
            }

            // online softmax: rows (q0+lg) and (q0+lg+8)
            float mx0 = NEG_BIG, mx1 = NEG_BIG;
#pragma unroll
            for (int ni = 0; ni < 8; ni++) {
                mx0 = fmaxf(mx0, fmaxf(sc[ni][0], sc[ni][1]));
                mx1 = fmaxf(mx1, fmaxf(sc[ni][2], sc[ni][3]));
            }
            mx0 = fmaxf(mx0, __shfl_xor_sync(0xffffffffu, mx0, 1));
            mx0 = fmaxf(mx0, __shfl_xor_sync(0xffffffffu, mx0, 2));
            mx1 = fmaxf(mx1, __shfl_xor_sync(0xffffffffu, mx1, 1));
            mx1 = fmaxf(mx1, __shfl_xor_sync(0xffffffffu, mx1, 2));
            float nm0 = fmaxf(m0, mx0), nm1 = fmaxf(m1, mx1);
            float corr0 = __expf(m0 - nm0), corr1 = __expf(m1 - nm1);
            m0 = nm0; m1 = nm1;

            float s0 = 0.f, s1 = 0.f;
            int pr0 = (q0 + lg) * ALDS, pr1 = (q0 + lg + 8) * ALDS;
#pragma unroll
            for (int ni = 0; ni < 8; ni++) {
                int c = ni * 8 + lt * 2;
                float p00 = __expf(sc[ni][0] - m0), p01 = __expf(sc[ni][1] - m0);
                float p10 = __expf(sc[ni][2] - m1), p11 = __expf(sc[ni][3] - m1);
                s0 += p00 + p01; s1 += p10 + p11;
                uint2 u0 = {f2tf32(p00), f2tf32(p01)};
                uint2 u1 = {f2tf32(p10), f2tf32(p11)};
                *(uint2*)&Ps[pr0 + c] = u0;
                *(uint2*)&Ps[pr1 + c] = u1;
            }
            s0 += __shfl_xor_sync(0xffffffffu, s0, 1);
            s0 += __shfl_xor_sync(0xffffffffu, s0, 2);
            s1 += __shfl_xor_sync(0xffffffffu, s1, 1);
            s1 += __shfl_xor_sync(0xffffffffu, s1, 2);
            l0 = l0 * corr0 + s0;
            l1 = l1 * corr1 + s1;
#pragma unroll
            for (int d = 0; d < 8; d++) {
                acc[d][0] *= corr0; acc[d][1] *= corr0;
                acc[d][2] *= corr1; acc[d][3] *= corr1;
            }
            __syncwarp();

            // acc += P V : 8 d-tiles, k=64  (P rows warp-private)
#pragma unroll
            for (int ks = 0; ks < 8; ks++) {
                int rA = q0 + lg, cA = ks * 8 + lt;
                uint32_t a0 = Ps[rA * ALDS + cA];
                uint32_t a1 = Ps[(rA + 8) * ALDS + cA];
                uint32_t a2 = Ps[rA * ALDS + cA + 4];
                uint32_t a3 = Ps[(rA + 8) * ALDS + cA + 4];
#pragma unroll
                for (int di = 0; di < 8; di++) {
                    int cn = di * 8 + lg;
                    uint32_t b0 = Vs[(ks * 8 + lt) * ALDS + cn];
                    uint32_t b1 = Vs[(ks * 8 + lt + 4) * ALDS + cn];
                    mma_tf32(acc[di], a0, a1, a2, a3, b0, b1);
                }
            }
        }
        __syncthreads();
    }

    // epilogue
    float inv0 = 1.f / l0, inv1 = 1.f / l1;
    float* Og = O + ((size_t)(b * SEQ + qt * 128 + q0 + lg)) * (NH * DH) + h * DH;
#pragma unroll
    for (int di = 0; di < 8; di++) {
        int c = di * 8 + lt * 2;
        *(float2*)(Og + c) = make_float2(acc[di][0] * inv0, acc[di][1] * inv0);
        *(float2*)(Og + (size_t)8 * (NH * DH) + c) = make_float2(acc[di][2] * inv1, acc[di][3] * inv1);
    }
}

// ---------------------------------------------------------------------------
// kernel_launch
// ---------------------------------------------------------------------------
extern "C" void kernel_launch(void* const* d_in, const int* in_sizes, int n_in,
                              void* d_out, int out_size) {
    const float* residual = (const float*)d_in[0];
    const float* WQ = (const float*)d_in[1];
    const float* WK = (const float*)d_in[2];
    const float* WV = (const float*)d_in[3];
    const float* WO = (const float*)d_in[4];
    float* out = (float*)d_out;

    float *Qb, *Kb, *Vb, *AOb;
    cudaGetSymbolAddress((void**)&Qb, g_Q);
    cudaGetSymbolAddress((void**)&Kb, g_K);
    cudaGetSymbolAddress((void**)&Vb, g_V);
    cudaGetSymbolAddress((void**)&AOb, g_AO);

    size_t smem_nt = (size_t)4 * ABUF * 4;
    size_t smem_nn = ((size_t)2 * ABUF + 2 * BBUF) * 4;
    size_t smem_at = (size_t)384 * ALDS * 4;   // 104448 B
    static int attrs_set = 0;
    if (!attrs_set) {
        cudaFuncSetAttribute(gemm_qkv_tf32, cudaFuncAttributeMaxDynamicSharedMemorySize, (int)smem_nt);
        cudaFuncSetAttribute(gemm_nn_tf32, cudaFuncAttributeMaxDynamicSharedMemorySize, (int)smem_nn);
        cudaFuncSetAttribute(attn_tf32, cudaFuncAttributeMaxDynamicSharedMemorySize, (int)smem_at);
        attrs_set = 1;
    }

    // fused Q/K/V projection: grid.x = 16 (Q) + 4 (K) + 4 (V)
    gemm_qkv_tf32<<<dim3(24, T_TOK / 128), 256, smem_nt>>>(
        residual, WQ, WK, WV, Qb, Kb, Vb);

    attn_tf32<<<dim3(SEQ / 128, NH, 2), 256, smem_at>>>(Qb, Kb, Vb, AOb);

    gemm_nn_tf32<<<dim3(DMODEL / 128, T_TOK / 128), 256, smem_nn>>>(
        AOb, WO, out, T_TOK, DMODEL, DMODEL);
}

// round 10
// speedup vs baseline: 3.4033x; 1.0088x over previous
#include <cuda_runtime.h>
#include <cstdint>

// ---------------------------------------------------------------------------
// B=2, S=2048, D_MODEL=2048, N_HEADS=32, N_KV_HEADS=8, D_HEAD=64, T=4096
// ---------------------------------------------------------------------------
#define T_TOK 4096
#define DMODEL 2048
#define NH 32
#define NKV 8
#define DH 64
#define SEQ 2048

__device__ float g_Q[(size_t)T_TOK * (NH * DH)];
__device__ float g_K[(size_t)T_TOK * (NKV * DH)];
__device__ float g_V[(size_t)T_TOK * (NKV * DH)];
__device__ float g_AO[(size_t)T_TOK * (NH * DH)];

// ---------------------------------------------------------------------------
// helpers
// ---------------------------------------------------------------------------
__device__ __forceinline__ uint32_t f2tf32(float x) {
    uint32_t r;
    asm("cvt.rna.tf32.f32 %0, %1;" : "=r"(r) : "f"(x));
    return r;
}

__device__ __forceinline__ void mma_tf32(float c[4], uint32_t a0, uint32_t a1,
                                         uint32_t a2, uint32_t a3,
                                         uint32_t b0, uint32_t b1) {
    asm volatile(
        "mma.sync.aligned.m16n8k8.row.col.f32.tf32.tf32.f32 "
        "{%0,%1,%2,%3}, {%4,%5,%6,%7}, {%8,%9}, {%0,%1,%2,%3};"
        : "+f"(c[0]), "+f"(c[1]), "+f"(c[2]), "+f"(c[3])
        : "r"(a0), "r"(a1), "r"(a2), "r"(a3), "r"(b0), "r"(b1));
}

// ---------------------------------------------------------------------------
// Fused QKV tf32 GEMM (NT): C[M,Nx] = A[M,2048] * Wx[Nx,2048]^T
// blockIdx.x 0..15 -> W_Q (N=2048), 16..19 -> W_K, 20..23 -> W_V (N=512).
// BM=BN=128, BK=32, 256 thr, 8 warps 2x4, warp tile 64x32. Double-buffered.
// ---------------------------------------------------------------------------
#define GLDA 36
#define ABUF (128 * GLDA)

__global__ __launch_bounds__(256)
void gemm_qkv_tf32(const float* __restrict__ A,
                   const float* __restrict__ WQ, const float* __restrict__ WK,
                   const float* __restrict__ WV,
                   float* __restrict__ Qo, float* __restrict__ Ko,
                   float* __restrict__ Vo) {
    extern __shared__ uint32_t sm[];
    uint32_t* As = sm;
    uint32_t* Bs = sm + 2 * ABUF;

    const int bx = blockIdx.x;
    const float* Bmat;
    float* C;
    int N, cb0;
    if (bx < 16)      { Bmat = WQ; C = Qo; N = 2048; cb0 = bx; }
    else if (bx < 20) { Bmat = WK; C = Ko; N = 512;  cb0 = bx - 16; }
    else              { Bmat = WV; C = Vo; N = 512;  cb0 = bx - 20; }

    const int Kd = DMODEL;
    const int tid = threadIdx.x, lane = tid & 31, wid = tid >> 5;
    const int wm = wid >> 2, wn = wid & 3;
    const int lg = lane >> 2, lt = lane & 3;

    const float* Ab = A + (size_t)(blockIdx.y * 128) * Kd;
    const float* Bb = Bmat + (size_t)cb0 * 128 * Kd;

    float acc[4][4][4];
#pragma unroll
    for (int i = 0; i < 4; i++)
#pragma unroll
        for (int j = 0; j < 4; j++)
#pragma unroll
            for (int r = 0; r < 4; r++) acc[i][j][r] = 0.f;

    float4 pa[4], pb[4];
#define GLOAD(k0)                                                               \
    {                                                                           \
        _Pragma("unroll") for (int i = 0; i < 4; i++) {                         \
            int idx = tid + i * 256;                                            \
            pa[i] = *(const float4*)(Ab + (size_t)(idx >> 3) * Kd + (k0) + (idx & 7) * 4); \
            pb[i] = *(const float4*)(Bb + (size_t)(idx >> 3) * Kd + (k0) + (idx & 7) * 4); \
        }                                                                       \
    }
#define SSTORE(buf)                                                             \
    {                                                                           \
        _Pragma("unroll") for (int i = 0; i < 4; i++) {                         \
            int idx = tid + i * 256;                                            \
            uint4 qa = {f2tf32(pa[i].x), f2tf32(pa[i].y), f2tf32(pa[i].z), f2tf32(pa[i].w)}; \
            *(uint4*)&As[(buf)*ABUF + (idx >> 3) * GLDA + (idx & 7) * 4] = qa;  \
            uint4 qb = {f2tf32(pb[i].x), f2tf32(pb[i].y), f2tf32(pb[i].z), f2tf32(pb[i].w)}; \
            *(uint4*)&Bs[(buf)*ABUF + (idx >> 3) * GLDA + (idx & 7) * 4] = qb;  \
        }                                                                       \
    }

    GLOAD(0); SSTORE(0);
    __syncthreads();

    const int nsteps = Kd / 32;
    for (int t = 0; t < nsteps; t++) {
        if (t + 1 < nsteps) GLOAD((t + 1) * 32);
        const uint32_t* Acur = &As[(t & 1) * ABUF];
        const uint32_t* Bcur = &Bs[(t & 1) * ABUF];
#pragma unroll
        for (int ks = 0; ks < 4; ks++) {
            uint32_t af[4][4];
#pragma unroll
            for (int mi = 0; mi < 4; mi++) {
                int r = wm * 64 + mi * 16 + lg, c = ks * 8 + lt;
                af[mi][0] = Acur[r * GLDA + c];
                af[mi][1] = Acur[(r + 8) * GLDA + c];
                af[mi][2] = Acur[r * GLDA + c + 4];
                af[mi][3] = Acur[(r + 8) * GLDA + c + 4];
            }
#pragma unroll
            for (int ni = 0; ni < 4; ni++) {
                int cb = wn * 32 + ni * 8 + lg, ck = ks * 8 + lt;
                uint32_t b0 = Bcur[cb * GLDA + ck];
                uint32_t b1 = Bcur[cb * GLDA + ck + 4];
#pragma unroll
                for (int mi = 0; mi < 4; mi++)
                    mma_tf32(acc[mi][ni], af[mi][0], af[mi][1], af[mi][2], af[mi][3], b0, b1);
            }
        }
        if (t + 1 < nsteps) SSTORE((t + 1) & 1);
        __syncthreads();
    }

#pragma unroll
    for (int mi = 0; mi < 4; mi++) {
        int row = blockIdx.y * 128 + wm * 64 + mi * 16 + lg;
#pragma unroll
        for (int ni = 0; ni < 4; ni++) {
            int col = cb0 * 128 + wn * 32 + ni * 8 + lt * 2;
            *(float2*)(C + (size_t)row * N + col) = make_float2(acc[mi][ni][0], acc[mi][ni][1]);
            *(float2*)(C + (size_t)(row + 8) * N + col) = make_float2(acc[mi][ni][2], acc[mi][ni][3]);
        }
    }
#undef GLOAD
#undef SSTORE
}

// ---------------------------------------------------------------------------
// tf32 GEMM NN: C[M,N] = A[M,K] * B[K,N].  B tile row-major [32][132].
// ---------------------------------------------------------------------------
#define GLDB 132
#define BBUF (32 * GLDB)

__global__ __launch_bounds__(256)
void gemm_nn_tf32(const float* __restrict__ A, const float* __restrict__ B,
                  float* __restrict__ C, int M, int N, int K) {
    extern __shared__ uint32_t sm[];
    uint32_t* As = sm;
    uint32_t* Bs = sm + 2 * ABUF;

    const int tid = threadIdx.x, lane = tid & 31, wid = tid >> 5;
    const int wm = wid >> 2, wn = wid & 3;
    const int lg = lane >> 2, lt = lane & 3;

    const float* Ab = A + (size_t)(blockIdx.y * 128) * K;
    const float* Bb = B + blockIdx.x * 128;

    float acc[4][4][4];
#pragma unroll
    for (int i = 0; i < 4; i++)
#pragma unroll
        for (int j = 0; j < 4; j++)
#pragma unroll
            for (int r = 0; r < 4; r++) acc[i][j][r] = 0.f;

    float4 pa[4], pb[4];
#define GLOAD(k0)                                                               \
    {                                                                           \
        _Pragma("unroll") for (int i = 0; i < 4; i++) {                         \
            int idx = tid + i * 256;                                            \
            pa[i] = *(const float4*)(Ab + (size_t)(idx >> 3) * K + (k0) + (idx & 7) * 4); \
            pb[i] = *(const float4*)(Bb + (size_t)((k0) + (idx >> 5)) * N + (idx & 31) * 4); \
        }                                                                       \
    }
#define SSTORE(buf)                                                             \
    {                                                                           \
        _Pragma("unroll") for (int i = 0; i < 4; i++) {                         \
            int idx = tid + i * 256;                                            \
            uint4 qa = {f2tf32(pa[i].x), f2tf32(pa[i].y), f2tf32(pa[i].z), f2tf32(pa[i].w)}; \
            *(uint4*)&As[(buf)*ABUF + (idx >> 3) * GLDA + (idx & 7) * 4] = qa;  \
            uint4 qb = {f2tf32(pb[i].x), f2tf32(pb[i].y), f2tf32(pb[i].z), f2tf32(pb[i].w)}; \
            *(uint4*)&Bs[(buf)*BBUF + (idx >> 5) * GLDB + (idx & 31) * 4] = qb;  \
        }                                                                       \
    }

    GLOAD(0); SSTORE(0);
    __syncthreads();

    const int nsteps = K / 32;
    for (int t = 0; t < nsteps; t++) {
        if (t + 1 < nsteps) GLOAD((t + 1) * 32);
        const uint32_t* Acur = &As[(t & 1) * ABUF];
        const uint32_t* Bcur = &Bs[(t & 1) * BBUF];
#pragma unroll
        for (int ks = 0; ks < 4; ks++) {
            uint32_t af[4][4];
#pragma unroll
            for (int mi = 0; mi < 4; mi++) {
                int r = wm * 64 + mi * 16 + lg, c = ks * 8 + lt;
                af[mi][0] = Acur[r * GLDA + c];
                af[mi][1] = Acur[(r + 8) * GLDA + c];
                af[mi][2] = Acur[r * GLDA + c + 4];
                af[mi][3] = Acur[(r + 8) * GLDA + c + 4];
            }
#pragma unroll
            for (int ni = 0; ni < 4; ni++) {
                int cn = wn * 32 + ni * 8 + lg;
                uint32_t b0 = Bcur[(ks * 8 + lt) * GLDB + cn];
                uint32_t b1 = Bcur[(ks * 8 + lt + 4) * GLDB + cn];
#pragma unroll
                for (int mi = 0; mi < 4; mi++)
                    mma_tf32(acc[mi][ni], af[mi][0], af[mi][1], af[mi][2], af[mi][3], b0, b1);
            }
        }
        if (t + 1 < nsteps) SSTORE((t + 1) & 1);
        __syncthreads();
    }

#pragma unroll
    for (int mi = 0; mi < 4; mi++) {
        int row = blockIdx.y * 128 + wm * 64 + mi * 16 + lg;
#pragma unroll
        for (int ni = 0; ni < 4; ni++) {
            int col = blockIdx.x * 128 + wn * 32 + ni * 8 + lt * 2;
            *(float2*)(C + (size_t)row * N + col) = make_float2(acc[mi][ni][0], acc[mi][ni][1]);
            *(float2*)(C + (size_t)(row + 8) * N + col) = make_float2(acc[mi][ni][2], acc[mi][ni][3]);
        }
    }
#undef GLOAD
#undef SSTORE
}

// ---------------------------------------------------------------------------
// Flash attention, tf32 mma.sync. BM=128 Q rows, K tile 64, double-buffered
// K/V, ONE __syncthreads per K tile. 256 thr (8 warps); warp w owns q-rows
// [w*16, w*16+16). Grid (S/128, NH, B).
// Q fragments live in registers (loop-invariant) -> no Q SMEM tile.
// SMEM words: Ks[2][64][68], Vs[2][64][68], Ps[128][68]  (104448 B, 2 CTA/SM)
// ---------------------------------------------------------------------------
#define ALDS 68
#define KVT (64 * ALDS)
#define NEG_BIG (-1e30f)

__global__ __launch_bounds__(256)
void attn_tf32(const float* __restrict__ Q, const float* __restrict__ K,
               const float* __restrict__ V, float* __restrict__ O) {
    extern __shared__ uint32_t sm[];
    uint32_t* Ks = sm;              // [2][64*ALDS]
    uint32_t* Vs = sm + 2 * KVT;    // [2][64*ALDS]
    uint32_t* Ps = sm + 4 * KVT;    // [128*ALDS]

    const int qt = blockIdx.x, h = blockIdx.y, b = blockIdx.z;
    const int kvh = h >> 2;
    const int tid = threadIdx.x, lane = tid & 31, wid = tid >> 5;
    const int lg = lane >> 2, lt = lane & 3;
    const int q0 = wid * 16;

    const float* Qg = Q + ((size_t)(b * SEQ + qt * 128)) * (NH * DH) + h * DH;
    const float* Kg = K + ((size_t)b * SEQ) * (NKV * DH) + kvh * DH;
    const float* Vg = V + ((size_t)b * SEQ) * (NKV * DH) + kvh * DH;

    // loader geometry for K/V tiles (64 rows x 64 cols, 4 quads per thread)
    const int ldr = tid >> 4;            // 0..15 -> rows ldr, ldr+16, +32, +48
    const int ldc = (tid & 15) * 4;      // col quad

    // Q fragments: loop-invariant, straight from global (one-time cost)
    uint32_t qf[8][4];
    {
        const float* q0p = Qg + (size_t)(q0 + lg) * (NH * DH);
        const float* q1p = Qg + (size_t)(q0 + lg + 8) * (NH * DH);
#pragma unroll
        for (int ks = 0; ks < 8; ks++) {
            int c = ks * 8 + lt;
            qf[ks][0] = f2tf32(__ldg(q0p + c) * 0.125f);
            qf[ks][1] = f2tf32(__ldg(q1p + c) * 0.125f);
            qf[ks][2] = f2tf32(__ldg(q0p + c + 4) * 0.125f);
            qf[ks][3] = f2tf32(__ldg(q1p + c + 4) * 0.125f);
        }
    }

    float m0 = NEG_BIG, m1 = NEG_BIG, l0 = 0.f, l1 = 0.f;
    float acc[8][4];
#pragma unroll
    for (int d = 0; d < 8; d++)
#pragma unroll
        for (int r = 0; r < 4; r++) acc[d][r] = 0.f;

    const int ktmax = 2 * qt + 1;
    const int warp_qlast = qt * 128 + q0 + 15;

    float4 pk[4], pv[4];
#define GK(kt_)                                                                 \
    {                                                                           \
        _Pragma("unroll") for (int i = 0; i < 4; i++)                           \
            pk[i] = *(const float4*)(Kg + (size_t)((kt_) * 64 + ldr + i * 16) * (NKV * DH) + ldc); \
    }
#define GV(kt_)                                                                 \
    {                                                                           \
        _Pragma("unroll") for (int i = 0; i < 4; i++)                           \
            pv[i] = *(const float4*)(Vg + (size_t)((kt_) * 64 + ldr + i * 16) * (NKV * DH) + ldc); \
    }
#define SK(buf)                                                                 \
    {                                                                           \
        _Pragma("unroll") for (int i = 0; i < 4; i++) {                         \
            uint4 u = {f2tf32(pk[i].x), f2tf32(pk[i].y), f2tf32(pk[i].z), f2tf32(pk[i].w)}; \
            *(uint4*)&Ks[(buf)*KVT + (ldr + i * 16) * ALDS + ldc] = u;          \
        }                                                                       \
    }
#define SV(buf)                                                                 \
    {                                                                           \
        _Pragma("unroll") for (int i = 0; i < 4; i++) {                         \
            uint4 u = {f2tf32(pv[i].x), f2tf32(pv[i].y), f2tf32(pv[i].z), f2tf32(pv[i].w)}; \
            *(uint4*)&Vs[(buf)*KVT + (ldr + i * 16) * ALDS + ldc] = u;          \
        }                                                                       \
    }

    // prologue: tile 0 into buffer 0
    GK(0); SK(0); GV(0); SV(0);
    __syncthreads();

    for (int kt = 0; kt <= ktmax; kt++) {
        const int bsel = kt & 1;
        const bool next = (kt < ktmax);
        const bool active = (kt * 64 <= warp_qlast);
        const uint32_t* Kb = Ks + bsel * KVT;
        const uint32_t* Vb = Vs + bsel * KVT;

        if (next) GK(kt + 1);   // K loads in flight during scores

        float sc[8][4];
        if (active) {
#pragma unroll
            for (int ni = 0; ni < 8; ni++)
#pragma unroll
                for (int r = 0; r < 4; r++) sc[ni][r] = 0.f;
#pragma unroll
            for (int ks = 0; ks < 8; ks++) {
#pragma unroll
                for (int ni = 0; ni < 8; ni++) {
                    int rB = ni * 8 + lg, cB = ks * 8 + lt;
                    uint32_t b0 = Kb[rB * ALDS + cB];
                    uint32_t b1 = Kb[rB * ALDS + cB + 4];
                    mma_tf32(sc[ni], qf[ks][0], qf[ks][1], qf[ks][2], qf[ks][3], b0, b1);
                }
            }

            if (kt * 64 + 63 > qt * 128 + q0) {   // diagonal region: mask
                int r0g = qt * 128 + q0 + lg, r1g = r0g + 8;
#pragma unroll
                for (int ni = 0; ni < 8; ni++) {
                    int cg = kt * 64 + ni * 8 + lt * 2;
                    if (cg > r0g) sc[ni][0] = NEG_BIG;
                    if (cg + 1 > r0g) sc[ni][1] = NEG_BIG;
                    if (cg > r1g) sc[ni][2] = NEG_BIG;
                    if (cg + 1 > r1g) sc[ni][3] = NEG_BIG;
                }
            }
        }

        if (next) GV(kt + 1);   // V loads in flight during softmax + PV

        if (active) {
            float mx0 = NEG_BIG, mx1 = NEG_BIG;
#pragma unroll
            for (int ni = 0; ni < 8; ni++) {
                mx0 = fmaxf(mx0, fmaxf(sc[ni][0], sc[ni][1]));
                mx1 = fmaxf(mx1, fmaxf(sc[ni][2], sc[ni][3]));
            }
            mx0 = fmaxf(mx0, __shfl_xor_sync(0xffffffffu, mx0, 1));
            mx0 = fmaxf(mx0, __shfl_xor_sync(0xffffffffu, mx0, 2));
            mx1 = fmaxf(mx1, __shfl_xor_sync(0xffffffffu, mx1, 1));
            mx1 = fmaxf(mx1, __shfl_xor_sync(0xffffffffu, mx1, 2));
            float nm0 = fmaxf(m0, mx0), nm1 = fmaxf(m1, mx1);
            float corr0 = __expf(m0 - nm0), corr1 = __expf(m1 - nm1);
            m0 = nm0; m1 = nm1;

            float s0 = 0.f, s1 = 0.f;
            int pr0 = (q0 + lg) * ALDS, pr1 = (q0 + lg + 8) * ALDS;
#pragma unroll
            for (int ni = 0; ni < 8; ni++) {
                int c = ni * 8 + lt * 2;
                float p00 = __expf(sc[ni][0] - m0), p01 = __expf(sc[ni][1] - m0);
                float p10 = __expf(sc[ni][2] - m1), p11 = __expf(sc[ni][3] - m1);
                s0 += p00 + p01; s1 += p10 + p11;
                uint2 u0 = {f2tf32(p00), f2tf32(p01)};
                uint2 u1 = {f2tf32(p10), f2tf32(p11)};
                *(uint2*)&Ps[pr0 + c] = u0;
                *(uint2*)&Ps[pr1 + c] = u1;
            }
            s0 += __shfl_xor_sync(0xffffffffu, s0, 1);
            s0 += __shfl_xor_sync(0xffffffffu, s0, 2);
            s1 += __shfl_xor_sync(0xffffffffu, s1, 1);
            s1 += __shfl_xor_sync(0xffffffffu, s1, 2);
            l0 = l0 * corr0 + s0;
            l1 = l1 * corr1 + s1;
#pragma unroll
            for (int d = 0; d < 8; d++) {
                acc[d][0] *= corr0; acc[d][1] *= corr0;
                acc[d][2] *= corr1; acc[d][3] *= corr1;
            }
            __syncwarp();

            // acc += P V  (P rows warp-private)
#pragma unroll
            for (int ks = 0; ks < 8; ks++) {
                int rA = q0 + lg, cA = ks * 8 + lt;
                uint32_t a0 = Ps[rA * ALDS + cA];
                uint32_t a1 = Ps[(rA + 8) * ALDS + cA];
                uint32_t a2 = Ps[rA * ALDS + cA + 4];
                uint32_t a3 = Ps[(rA + 8) * ALDS + cA + 4];
#pragma unroll
                for (int di = 0; di < 8; di++) {
                    int cn = di * 8 + lg;
                    uint32_t b0 = Vb[(ks * 8 + lt) * ALDS + cn];
                    uint32_t b1 = Vb[(ks * 8 + lt + 4) * ALDS + cn];
                    mma_tf32(acc[di], a0, a1, a2, a3, b0, b1);
                }
            }
        }

        if (next) { SK(bsel ^ 1); SV(bsel ^ 1); }
        __syncthreads();
    }
#undef GK
#undef GV
#undef SK
#undef SV

    float inv0 = 1.f / l0, inv1 = 1.f / l1;
    float* Og = O + ((size_t)(b * SEQ + qt * 128 + q0 + lg)) * (NH * DH) + h * DH;
#pragma unroll
    for (int di = 0; di < 8; di++) {
        int c = di * 8 + lt * 2;
        *(float2*)(Og + c) = make_float2(acc[di][0] * inv0, acc[di][1] * inv0);
        *(float2*)(Og + (size_t)8 * (NH * DH) + c) = make_float2(acc[di][2] * inv1, acc[di][3] * inv1);
    }
}

// ---------------------------------------------------------------------------
// kernel_launch
// ---------------------------------------------------------------------------
extern "C" void kernel_launch(void* const* d_in, const int* in_sizes, int n_in,
                              void* d_out, int out_size) {
    const float* residual = (const float*)d_in[0];
    const float* WQ = (const float*)d_in[1];
    const float* WK = (const float*)d_in[2];
    const float* WV = (const float*)d_in[3];
    const float* WO = (const float*)d_in[4];
    float* out = (float*)d_out;

    float *Qb, *Kb, *Vb, *AOb;
    cudaGetSymbolAddress((void**)&Qb, g_Q);
    cudaGetSymbolAddress((void**)&Kb, g_K);
    cudaGetSymbolAddress((void**)&Vb, g_V);
    cudaGetSymbolAddress((void**)&AOb, g_AO);

    size_t smem_nt = (size_t)4 * ABUF * 4;
    size_t smem_nn = ((size_t)2 * ABUF + 2 * BBUF) * 4;
    size_t smem_at = ((size_t)4 * KVT + 128 * ALDS) * 4;   // 104448 B
    static int attrs_set = 0;
    if (!attrs_set) {
        cudaFuncSetAttribute(gemm_qkv_tf32, cudaFuncAttributeMaxDynamicSharedMemorySize, (int)smem_nt);
        cudaFuncSetAttribute(gemm_nn_tf32, cudaFuncAttributeMaxDynamicSharedMemorySize, (int)smem_nn);
        cudaFuncSetAttribute(attn_tf32, cudaFuncAttributeMaxDynamicSharedMemorySize, (int)smem_at);
        attrs_set = 1;
    }

    gemm_qkv_tf32<<<dim3(24, T_TOK / 128), 256, smem_nt>>>(
        residual, WQ, WK, WV, Qb, Kb, Vb);

    attn_tf32<<<dim3(SEQ / 128, NH, 2), 256, smem_at>>>(Qb, Kb, Vb, AOb);

    gemm_nn_tf32<<<dim3(DMODEL / 128, T_TOK / 128), 256, smem_nn>>>(
        AOb, WO, out, T_TOK, DMODEL, DMODEL);
}

// round 11
// speedup vs baseline: 3.4896x; 1.0253x over previous
#include <cuda_runtime.h>
#include <cstdint>

// ---------------------------------------------------------------------------
// B=2, S=2048, D_MODEL=2048, N_HEADS=32, N_KV_HEADS=8, D_HEAD=64, T=4096
// ---------------------------------------------------------------------------
#define T_TOK 4096
#define DMODEL 2048
#define NH 32
#define NKV 8
#define DH 64
#define SEQ 2048

__device__ float g_Q[(size_t)T_TOK * (NH * DH)];
__device__ float g_K[(size_t)T_TOK * (NKV * DH)];
__device__ float g_V[(size_t)T_TOK * (NKV * DH)];
__device__ float g_AO[(size_t)T_TOK * (NH * DH)];

// ---------------------------------------------------------------------------
// helpers
// ---------------------------------------------------------------------------
__device__ __forceinline__ uint32_t f2tf32(float x) {
    uint32_t r;
    asm("cvt.rna.tf32.f32 %0, %1;" : "=r"(r) : "f"(x));
    return r;
}

__device__ __forceinline__ void mma_tf32(float c[4], uint32_t a0, uint32_t a1,
                                         uint32_t a2, uint32_t a3,
                                         uint32_t b0, uint32_t b1) {
    asm volatile(
        "mma.sync.aligned.m16n8k8.row.col.f32.tf32.tf32.f32 "
        "{%0,%1,%2,%3}, {%4,%5,%6,%7}, {%8,%9}, {%0,%1,%2,%3};"
        : "+f"(c[0]), "+f"(c[1]), "+f"(c[2]), "+f"(c[3])
        : "r"(a0), "r"(a1), "r"(a2), "r"(a3), "r"(b0), "r"(b1));
}

// ---------------------------------------------------------------------------
// Fused QKV tf32 GEMM (NT): C[M,Nx] = A[M,2048] * Wx[Nx,2048]^T
// blockIdx.x 0..15 -> W_Q (N=2048), 16..19 -> W_K, 20..23 -> W_V (N=512).
// BM=BN=128, BK=32, 256 thr, 8 warps 2x4, warp tile 64x32. Double-buffered.
// ---------------------------------------------------------------------------
#define GLDA 36
#define ABUF (128 * GLDA)

__global__ __launch_bounds__(256)
void gemm_qkv_tf32(const float* __restrict__ A,
                   const float* __restrict__ WQ, const float* __restrict__ WK,
                   const float* __restrict__ WV,
                   float* __restrict__ Qo, float* __restrict__ Ko,
                   float* __restrict__ Vo) {
    extern __shared__ uint32_t sm[];
    uint32_t* As = sm;
    uint32_t* Bs = sm + 2 * ABUF;

    const int bx = blockIdx.x;
    const float* Bmat;
    float* C;
    int N, cb0;
    if (bx < 16)      { Bmat = WQ; C = Qo; N = 2048; cb0 = bx; }
    else if (bx < 20) { Bmat = WK; C = Ko; N = 512;  cb0 = bx - 16; }
    else              { Bmat = WV; C = Vo; N = 512;  cb0 = bx - 20; }

    const int Kd = DMODEL;
    const int tid = threadIdx.x, lane = tid & 31, wid = tid >> 5;
    const int wm = wid >> 2, wn = wid & 3;
    const int lg = lane >> 2, lt = lane & 3;

    const float* Ab = A + (size_t)(blockIdx.y * 128) * Kd;
    const float* Bb = Bmat + (size_t)cb0 * 128 * Kd;

    float acc[4][4][4];
#pragma unroll
    for (int i = 0; i < 4; i++)
#pragma unroll
        for (int j = 0; j < 4; j++)
#pragma unroll
            for (int r = 0; r < 4; r++) acc[i][j][r] = 0.f;

    float4 pa[4], pb[4];
#define GLOAD(k0)                                                               \
    {                                                                           \
        _Pragma("unroll") for (int i = 0; i < 4; i++) {                         \
            int idx = tid + i * 256;                                            \
            pa[i] = *(const float4*)(Ab + (size_t)(idx >> 3) * Kd + (k0) + (idx & 7) * 4); \
            pb[i] = *(const float4*)(Bb + (size_t)(idx >> 3) * Kd + (k0) + (idx & 7) * 4); \
        }                                                                       \
    }
#define SSTORE(buf)                                                             \
    {                                                                           \
        _Pragma("unroll") for (int i = 0; i < 4; i++) {                         \
            int idx = tid + i * 256;                                            \
            uint4 qa = {f2tf32(pa[i].x), f2tf32(pa[i].y), f2tf32(pa[i].z), f2tf32(pa[i].w)}; \
            *(uint4*)&As[(buf)*ABUF + (idx >> 3) * GLDA + (idx & 7) * 4] = qa;  \
            uint4 qb = {f2tf32(pb[i].x), f2tf32(pb[i].y), f2tf32(pb[i].z), f2tf32(pb[i].w)}; \
            *(uint4*)&Bs[(buf)*ABUF + (idx >> 3) * GLDA + (idx & 7) * 4] = qb;  \
        }                                                                       \
    }

    GLOAD(0); SSTORE(0);
    __syncthreads();

    const int nsteps = Kd / 32;
    for (int t = 0; t < nsteps; t++) {
        if (t + 1 < nsteps) GLOAD((t + 1) * 32);
        const uint32_t* Acur = &As[(t & 1) * ABUF];
        const uint32_t* Bcur = &Bs[(t & 1) * ABUF];
#pragma unroll
        for (int ks = 0; ks < 4; ks++) {
            uint32_t af[4][4];
#pragma unroll
            for (int mi = 0; mi < 4; mi++) {
                int r = wm * 64 + mi * 16 + lg, c = ks * 8 + lt;
                af[mi][0] = Acur[r * GLDA + c];
                af[mi][1] = Acur[(r + 8) * GLDA + c];
                af[mi][2] = Acur[r * GLDA + c + 4];
                af[mi][3] = Acur[(r + 8) * GLDA + c + 4];
            }
#pragma unroll
            for (int ni = 0; ni < 4; ni++) {
                int cb = wn * 32 + ni * 8 + lg, ck = ks * 8 + lt;
                uint32_t b0 = Bcur[cb * GLDA + ck];
                uint32_t b1 = Bcur[cb * GLDA + ck + 4];
#pragma unroll
                for (int mi = 0; mi < 4; mi++)
                    mma_tf32(acc[mi][ni], af[mi][0], af[mi][1], af[mi][2], af[mi][3], b0, b1);
            }
        }
        if (t + 1 < nsteps) SSTORE((t + 1) & 1);
        __syncthreads();
    }

#pragma unroll
    for (int mi = 0; mi < 4; mi++) {
        int row = blockIdx.y * 128 + wm * 64 + mi * 16 + lg;
#pragma unroll
        for (int ni = 0; ni < 4; ni++) {
            int col = cb0 * 128 + wn * 32 + ni * 8 + lt * 2;
            *(float2*)(C + (size_t)row * N + col) = make_float2(acc[mi][ni][0], acc[mi][ni][1]);
            *(float2*)(C + (size_t)(row + 8) * N + col) = make_float2(acc[mi][ni][2], acc[mi][ni][3]);
        }
    }
#undef GLOAD
#undef SSTORE
}

// ---------------------------------------------------------------------------
// tf32 GEMM NN: C[M,N] = A[M,K] * B[K,N].  B tile row-major [32][132].
// ---------------------------------------------------------------------------
#define GLDB 132
#define BBUF (32 * GLDB)

__global__ __launch_bounds__(256)
void gemm_nn_tf32(const float* __restrict__ A, const float* __restrict__ B,
                  float* __restrict__ C, int M, int N, int K) {
    extern __shared__ uint32_t sm[];
    uint32_t* As = sm;
    uint32_t* Bs = sm + 2 * ABUF;

    const int tid = threadIdx.x, lane = tid & 31, wid = tid >> 5;
    const int wm = wid >> 2, wn = wid & 3;
    const int lg = lane >> 2, lt = lane & 3;

    const float* Ab = A + (size_t)(blockIdx.y * 128) * K;
    const float* Bb = B + blockIdx.x * 128;

    float acc[4][4][4];
#pragma unroll
    for (int i = 0; i < 4; i++)
#pragma unroll
        for (int j = 0; j < 4; j++)
#pragma unroll
            for (int r = 0; r < 4; r++) acc[i][j][r] = 0.f;

    float4 pa[4], pb[4];
#define GLOAD(k0)                                                               \
    {                                                                           \
        _Pragma("unroll") for (int i = 0; i < 4; i++) {                         \
            int idx = tid + i * 256;                                            \
            pa[i] = *(const float4*)(Ab + (size_t)(idx >> 3) * K + (k0) + (idx & 7) * 4); \
            pb[i] = *(const float4*)(Bb + (size_t)((k0) + (idx >> 5)) * N + (idx & 31) * 4); \
        }                                                                       \
    }
#define SSTORE(buf)                                                             \
    {                                                                           \
        _Pragma("unroll") for (int i = 0; i < 4; i++) {                         \
            int idx = tid + i * 256;                                            \
            uint4 qa = {f2tf32(pa[i].x), f2tf32(pa[i].y), f2tf32(pa[i].z), f2tf32(pa[i].w)}; \
            *(uint4*)&As[(buf)*ABUF + (idx >> 3) * GLDA + (idx & 7) * 4] = qa;  \
            uint4 qb = {f2tf32(pb[i].x), f2tf32(pb[i].y), f2tf32(pb[i].z), f2tf32(pb[i].w)}; \
            *(uint4*)&Bs[(buf)*BBUF + (idx >> 5) * GLDB + (idx & 31) * 4] = qb;  \
        }                                                                       \
    }

    GLOAD(0); SSTORE(0);
    __syncthreads();

    const int nsteps = K / 32;
    for (int t = 0; t < nsteps; t++) {
        if (t + 1 < nsteps) GLOAD((t + 1) * 32);
        const uint32_t* Acur = &As[(t & 1) * ABUF];
        const uint32_t* Bcur = &Bs[(t & 1) * BBUF];
#pragma unroll
        for (int ks = 0; ks < 4; ks++) {
            uint32_t af[4][4];
#pragma unroll
            for (int mi = 0; mi < 4; mi++) {
                int r = wm * 64 + mi * 16 + lg, c = ks * 8 + lt;
                af[mi][0] = Acur[r * GLDA + c];
                af[mi][1] = Acur[(r + 8) * GLDA + c];
                af[mi][2] = Acur[r * GLDA + c + 4];
                af[mi][3] = Acur[(r + 8) * GLDA + c + 4];
            }
#pragma unroll
            for (int ni = 0; ni < 4; ni++) {
                int cn = wn * 32 + ni * 8 + lg;
                uint32_t b0 = Bcur[(ks * 8 + lt) * GLDB + cn];
                uint32_t b1 = Bcur[(ks * 8 + lt + 4) * GLDB + cn];
#pragma unroll
                for (int mi = 0; mi < 4; mi++)
                    mma_tf32(acc[mi][ni], af[mi][0], af[mi][1], af[mi][2], af[mi][3], b0, b1);
            }
        }
        if (t + 1 < nsteps) SSTORE((t + 1) & 1);
        __syncthreads();
    }

#pragma unroll
    for (int mi = 0; mi < 4; mi++) {
        int row = blockIdx.y * 128 + wm * 64 + mi * 16 + lg;
#pragma unroll
        for (int ni = 0; ni < 4; ni++) {
            int col = blockIdx.x * 128 + wn * 32 + ni * 8 + lt * 2;
            *(float2*)(C + (size_t)row * N + col) = make_float2(acc[mi][ni][0], acc[mi][ni][1]);
            *(float2*)(C + (size_t)(row + 8) * N + col) = make_float2(acc[mi][ni][2], acc[mi][ni][3]);
        }
    }
#undef GLOAD
#undef SSTORE
}

// ---------------------------------------------------------------------------
// Flash attention, tf32 mma.sync. BM=128 Q rows, K tile 64.
// 256 thr (8 warps); warp w owns q-rows [w*16, w*16+16). Grid (S/128, NH, B).
// Q fragments in registers (loop-invariant) -> no Q SMEM tile.
// Single-buffered K/V + P: SMEM = 68*(128+128)*4 = 69,632 B -> 2 CTAs/SM.
// LPT scheduling: qt = gridDim.x-1-blockIdx.x (heavy CTAs launch first).
// __launch_bounds__(256, 2) caps regs at 128 for the 2-CTA residency.
// ---------------------------------------------------------------------------
#define ALDS 68
#define KVT (64 * ALDS)
#define NEG_BIG (-1e30f)

__global__ __launch_bounds__(256, 2)
void attn_tf32(const float* __restrict__ Q, const float* __restrict__ K,
               const float* __restrict__ V, float* __restrict__ O) {
    extern __shared__ uint32_t sm[];
    uint32_t* Ks = sm;              // [64*ALDS]
    uint32_t* Vs = sm + KVT;        // [64*ALDS]
    uint32_t* Ps = sm + 2 * KVT;    // [128*ALDS]

    const int qt = gridDim.x - 1 - blockIdx.x;   // LPT: heavy first
    const int h = blockIdx.y, b = blockIdx.z;
    const int kvh = h >> 2;
    const int tid = threadIdx.x, lane = tid & 31, wid = tid >> 5;
    const int lg = lane >> 2, lt = lane & 3;
    const int q0 = wid * 16;

    const float* Qg = Q + ((size_t)(b * SEQ + qt * 128)) * (NH * DH) + h * DH;
    const float* Kg = K + ((size_t)b * SEQ) * (NKV * DH) + kvh * DH;
    const float* Vg = V + ((size_t)b * SEQ) * (NKV * DH) + kvh * DH;

    // loader geometry (64x64 tile, 4 row-strided float4 per thread)
    const int ldr = tid >> 4;            // 0..15
    const int ldc = (tid & 15) * 4;

    // Q fragments: loop-invariant, from global once
    uint32_t qf[8][4];
    {
        const float* q0p = Qg + (size_t)(q0 + lg) * (NH * DH);
        const float* q1p = Qg + (size_t)(q0 + lg + 8) * (NH * DH);
#pragma unroll
        for (int ks = 0; ks < 8; ks++) {
            int c = ks * 8 + lt;
            qf[ks][0] = f2tf32(__ldg(q0p + c) * 0.125f);
            qf[ks][1] = f2tf32(__ldg(q1p + c) * 0.125f);
            qf[ks][2] = f2tf32(__ldg(q0p + c + 4) * 0.125f);
            qf[ks][3] = f2tf32(__ldg(q1p + c + 4) * 0.125f);
        }
    }

    float m0 = NEG_BIG, m1 = NEG_BIG, l0 = 0.f, l1 = 0.f;
    float acc[8][4];
#pragma unroll
    for (int d = 0; d < 8; d++)
#pragma unroll
        for (int r = 0; r < 4; r++) acc[d][r] = 0.f;

    const int ktmax = 2 * qt + 1;
    const int warp_qlast = qt * 128 + q0 + 15;

    for (int kt = 0; kt <= ktmax; kt++) {
        // load K,V tile kt (128b LDG, cvt, 128b STS)
#pragma unroll
        for (int i = 0; i < 4; i++) {
            int r = ldr + i * 16;
            float4 kv = *(const float4*)(Kg + (size_t)(kt * 64 + r) * (NKV * DH) + ldc);
            float4 vv = *(const float4*)(Vg + (size_t)(kt * 64 + r) * (NKV * DH) + ldc);
            uint4 ku = {f2tf32(kv.x), f2tf32(kv.y), f2tf32(kv.z), f2tf32(kv.w)};
            uint4 vu = {f2tf32(vv.x), f2tf32(vv.y), f2tf32(vv.z), f2tf32(vv.w)};
            *(uint4*)&Ks[r * ALDS + ldc] = ku;
            *(uint4*)&Vs[r * ALDS + ldc] = vu;
        }
        __syncthreads();

        if (kt * 64 <= warp_qlast) {      // tile not fully masked for this warp
            float sc[8][4];
#pragma unroll
            for (int ni = 0; ni < 8; ni++)
#pragma unroll
                for (int r = 0; r < 4; r++) sc[ni][r] = 0.f;
#pragma unroll
            for (int ks = 0; ks < 8; ks++) {
#pragma unroll
                for (int ni = 0; ni < 8; ni++) {
                    int rB = ni * 8 + lg, cB = ks * 8 + lt;
                    uint32_t b0 = Ks[rB * ALDS + cB];
                    uint32_t b1 = Ks[rB * ALDS + cB + 4];
                    mma_tf32(sc[ni], qf[ks][0], qf[ks][1], qf[ks][2], qf[ks][3], b0, b1);
                }
            }

            if (kt * 64 + 63 > qt * 128 + q0) {   // diagonal region: mask
                int r0g = qt * 128 + q0 + lg, r1g = r0g + 8;
#pragma unroll
                for (int ni = 0; ni < 8; ni++) {
                    int cg = kt * 64 + ni * 8 + lt * 2;
                    if (cg > r0g) sc[ni][0] = NEG_BIG;
                    if (cg + 1 > r0g) sc[ni][1] = NEG_BIG;
                    if (cg > r1g) sc[ni][2] = NEG_BIG;
                    if (cg + 1 > r1g) sc[ni][3] = NEG_BIG;
                }
            }

            // online softmax: rows (q0+lg), (q0+lg+8)
            float mx0 = NEG_BIG, mx1 = NEG_BIG;
#pragma unroll
            for (int ni = 0; ni < 8; ni++) {
                mx0 = fmaxf(mx0, fmaxf(sc[ni][0], sc[ni][1]));
                mx1 = fmaxf(mx1, fmaxf(sc[ni][2], sc[ni][3]));
            }
            mx0 = fmaxf(mx0, __shfl_xor_sync(0xffffffffu, mx0, 1));
            mx0 = fmaxf(mx0, __shfl_xor_sync(0xffffffffu, mx0, 2));
            mx1 = fmaxf(mx1, __shfl_xor_sync(0xffffffffu, mx1, 1));
            mx1 = fmaxf(mx1, __shfl_xor_sync(0xffffffffu, mx1, 2));
            float nm0 = fmaxf(m0, mx0), nm1 = fmaxf(m1, mx1);
            float corr0 = __expf(m0 - nm0), corr1 = __expf(m1 - nm1);
            m0 = nm0; m1 = nm1;

            float s0 = 0.f, s1 = 0.f;
            int pr0 = (q0 + lg) * ALDS, pr1 = (q0 + lg + 8) * ALDS;
#pragma unroll
            for (int ni = 0; ni < 8; ni++) {
                int c = ni * 8 + lt * 2;
                float p00 = __expf(sc[ni][0] - m0), p01 = __expf(sc[ni][1] - m0);
                float p10 = __expf(sc[ni][2] - m1), p11 = __expf(sc[ni][3] - m1);
                s0 += p00 + p01; s1 += p10 + p11;
                uint2 u0 = {f2tf32(p00), f2tf32(p01)};
                uint2 u1 = {f2tf32(p10), f2tf32(p11)};
                *(uint2*)&Ps[pr0 + c] = u0;
                *(uint2*)&Ps[pr1 + c] = u1;
            }
            s0 += __shfl_xor_sync(0xffffffffu, s0, 1);
            s0 += __shfl_xor_sync(0xffffffffu, s0, 2);
            s1 += __shfl_xor_sync(0xffffffffu, s1, 1);
            s1 += __shfl_xor_sync(0xffffffffu, s1, 2);
            l0 = l0 * corr0 + s0;
            l1 = l1 * corr1 + s1;
#pragma unroll
            for (int d = 0; d < 8; d++) {
                acc[d][0] *= corr0; acc[d][1] *= corr0;
                acc[d][2] *= corr1; acc[d][3] *= corr1;
            }
            __syncwarp();

            // acc += P V  (P rows warp-private)
#pragma unroll
            for (int ks = 0; ks < 8; ks++) {
                int rA = q0 + lg, cA = ks * 8 + lt;
                uint32_t a0 = Ps[rA * ALDS + cA];
                uint32_t a1 = Ps[(rA + 8) * ALDS + cA];
                uint32_t a2 = Ps[rA * ALDS + cA + 4];
                uint32_t a3 = Ps[(rA + 8) * ALDS + cA + 4];
#pragma unroll
                for (int di = 0; di < 8; di++) {
                    int cn = di * 8 + lg;
                    uint32_t b0 = Vs[(ks * 8 + lt) * ALDS + cn];
                    uint32_t b1 = Vs[(ks * 8 + lt + 4) * ALDS + cn];
                    mma_tf32(acc[di], a0, a1, a2, a3, b0, b1);
                }
            }
        }
        __syncthreads();
    }

    float inv0 = 1.f / l0, inv1 = 1.f / l1;
    float* Og = O + ((size_t)(b * SEQ + qt * 128 + q0 + lg)) * (NH * DH) + h * DH;
#pragma unroll
    for (int di = 0; di < 8; di++) {
        int c = di * 8 + lt * 2;
        *(float2*)(Og + c) = make_float2(acc[di][0] * inv0, acc[di][1] * inv0);
        *(float2*)(Og + (size_t)8 * (NH * DH) + c) = make_float2(acc[di][2] * inv1, acc[di][3] * inv1);
    }
}

// ---------------------------------------------------------------------------
// kernel_launch
// ---------------------------------------------------------------------------
extern "C" void kernel_launch(void* const* d_in, const int* in_sizes, int n_in,
                              void* d_out, int out_size) {
    const float* residual = (const float*)d_in[0];
    const float* WQ = (const float*)d_in[1];
    const float* WK = (const float*)d_in[2];
    const float* WV = (const float*)d_in[3];
    const float* WO = (const float*)d_in[4];
    float* out = (float*)d_out;

    float *Qb, *Kb, *Vb, *AOb;
    cudaGetSymbolAddress((void**)&Qb, g_Q);
    cudaGetSymbolAddress((void**)&Kb, g_K);
    cudaGetSymbolAddress((void**)&Vb, g_V);
    cudaGetSymbolAddress((void**)&AOb, g_AO);

    size_t smem_nt = (size_t)4 * ABUF * 4;
    size_t smem_nn = ((size_t)2 * ABUF + 2 * BBUF) * 4;
    size_t smem_at = ((size_t)2 * KVT + 128 * ALDS) * 4;   // 69,632 B
    static int attrs_set = 0;
    if (!attrs_set) {
        cudaFuncSetAttribute(gemm_qkv_tf32, cudaFuncAttributeMaxDynamicSharedMemorySize, (int)smem_nt);
        cudaFuncSetAttribute(gemm_nn_tf32, cudaFuncAttributeMaxDynamicSharedMemorySize, (int)smem_nn);
        cudaFuncSetAttribute(attn_tf32, cudaFuncAttributeMaxDynamicSharedMemorySize, (int)smem_at);
        attrs_set = 1;
    }

    gemm_qkv_tf32<<<dim3(24, T_TOK / 128), 256, smem_nt>>>(
        residual, WQ, WK, WV, Qb, Kb, Vb);

    attn_tf32<<<dim3(SEQ / 128, NH, 2), 256, smem_at>>>(Qb, Kb, Vb, AOb);

    gemm_nn_tf32<<<dim3(DMODEL / 128, T_TOK / 128), 256, smem_nn>>>(
        AOb, WO, out, T_TOK, DMODEL, DMODEL);
}

// round 12
// speedup vs baseline: 3.7361x; 1.0706x over previous
#include <cuda_runtime.h>
#include <cstdint>

// ---------------------------------------------------------------------------
// B=2, S=2048, D_MODEL=2048, N_HEADS=32, N_KV_HEADS=8, D_HEAD=64, T=4096
// ---------------------------------------------------------------------------
#define T_TOK 4096
#define DMODEL 2048
#define NH 32
#define NKV 8
#define DH 64
#define SEQ 2048

// scratch
__device__ float g_Q[(size_t)T_TOK * (NH * DH)];
__device__ float g_K[(size_t)T_TOK * (NKV * DH)];
__device__ float g_V[(size_t)T_TOK * (NKV * DH)];
__device__ float g_AO[(size_t)T_TOK * (NH * DH)];
__device__ float g_RES[(size_t)T_TOK * DMODEL];       // residual, tf32-rounded
__device__ float g_WQr[(size_t)NH * DH * DMODEL];
__device__ float g_WKr[(size_t)NKV * DH * DMODEL];
__device__ float g_WVr[(size_t)NKV * DH * DMODEL];
__device__ float g_WOr[(size_t)NH * DH * DMODEL];

// ---------------------------------------------------------------------------
// helpers
// ---------------------------------------------------------------------------
__device__ __forceinline__ uint32_t f2tf32(float x) {
    uint32_t r;
    asm("cvt.rna.tf32.f32 %0, %1;" : "=r"(r) : "f"(x));
    return r;
}

__device__ __forceinline__ uint32_t smem_u32(const void* p) {
    uint32_t a;
    asm("{ .reg .u64 t; cvta.to.shared.u64 t, %1; cvt.u32.u64 %0, t; }"
        : "=r"(a) : "l"(p));
    return a;
}

__device__ __forceinline__ void cp_async16(uint32_t dst, const void* src) {
    asm volatile("cp.async.cg.shared.global [%0], [%1], 16;"
                 :: "r"(dst), "l"(src));
}
#define CP_COMMIT() asm volatile("cp.async.commit_group;" ::: "memory")
#define CP_WAIT(n)  asm volatile("cp.async.wait_group %0;" :: "n"(n) : "memory")

__device__ __forceinline__ void mma_tf32(float c[4], uint32_t a0, uint32_t a1,
                                         uint32_t a2, uint32_t a3,
                                         uint32_t b0, uint32_t b1) {
    asm volatile(
        "mma.sync.aligned.m16n8k8.row.col.f32.tf32.tf32.f32 "
        "{%0,%1,%2,%3}, {%4,%5,%6,%7}, {%8,%9}, {%0,%1,%2,%3};"
        : "+f"(c[0]), "+f"(c[1]), "+f"(c[2]), "+f"(c[3])
        : "r"(a0), "r"(a1), "r"(a2), "r"(a3), "r"(b0), "r"(b1));
}

// ---------------------------------------------------------------------------
// tf32 pre-round: out[i] = rna_tf32(in[i]); n multiple of 1024
// ---------------------------------------------------------------------------
__global__ __launch_bounds__(256)
void round_tf32(const float* __restrict__ in, float* __restrict__ out) {
    size_t i = ((size_t)blockIdx.x * 256 + threadIdx.x) * 4;
    float4 v = *(const float4*)(in + i);
    uint4 u = {f2tf32(v.x), f2tf32(v.y), f2tf32(v.z), f2tf32(v.w)};
    *(float4*)(out + i) = *(float4*)&u;
}

// ---------------------------------------------------------------------------
// Fused QKV tf32 GEMM (NT), cp.async edition.
// Inputs pre-rounded to tf32 -> no cvt, no STS in the loop.
// Outputs written tf32-rounded (consumed by attention as tf32 anyway).
// blockIdx.x 0..15 -> W_Q (N=2048), 16..19 -> W_K, 20..23 -> W_V (N=512).
// BM=BN=128, BK=32, 256 thr, 8 warps 2x4, warp tile 64x32. Double-buffered.
// ---------------------------------------------------------------------------
#define GLDA 36
#define ABUF (128 * GLDA)

__global__ __launch_bounds__(256)
void gemm_qkv_tf32(const float* __restrict__ A,
                   const float* __restrict__ WQ, const float* __restrict__ WK,
                   const float* __restrict__ WV,
                   float* __restrict__ Qo, float* __restrict__ Ko,
                   float* __restrict__ Vo) {
    extern __shared__ uint32_t sm[];
    uint32_t* As = sm;
    uint32_t* Bs = sm + 2 * ABUF;
    const uint32_t saA = smem_u32(sm);
    const uint32_t saB = saA + 2 * ABUF * 4;

    const int bx = blockIdx.x;
    const float* Bmat;
    float* C;
    int N, cb0;
    if (bx < 16)      { Bmat = WQ; C = Qo; N = 2048; cb0 = bx; }
    else if (bx < 20) { Bmat = WK; C = Ko; N = 512;  cb0 = bx - 16; }
    else              { Bmat = WV; C = Vo; N = 512;  cb0 = bx - 20; }

    const int Kd = DMODEL;
    const int tid = threadIdx.x, lane = tid & 31, wid = tid >> 5;
    const int wm = wid >> 2, wn = wid & 3;
    const int lg = lane >> 2, lt = lane & 3;

    const float* Ab = A + (size_t)(blockIdx.y * 128) * Kd;
    const float* Bb = Bmat + (size_t)cb0 * 128 * Kd;

    float acc[4][4][4];
#pragma unroll
    for (int i = 0; i < 4; i++)
#pragma unroll
        for (int j = 0; j < 4; j++)
#pragma unroll
            for (int r = 0; r < 4; r++) acc[i][j][r] = 0.f;

#define ISSUE(k0, buf)                                                          \
    {                                                                           \
        _Pragma("unroll") for (int i = 0; i < 4; i++) {                         \
            int idx = tid + i * 256;                                            \
            int rw = idx >> 3, cq = (idx & 7) * 4;                              \
            uint32_t so = (uint32_t)(rw * GLDA + cq) * 4;                       \
            cp_async16(saA + (buf) * (ABUF * 4) + so,                           \
                       Ab + (size_t)rw * Kd + (k0) + cq);                       \
            cp_async16(saB + (buf) * (ABUF * 4) + so,                           \
                       Bb + (size_t)rw * Kd + (k0) + cq);                       \
        }                                                                       \
    }

    ISSUE(0, 0); CP_COMMIT();

    const int nsteps = Kd / 32;
    for (int t = 0; t < nsteps; t++) {
        if (t + 1 < nsteps) { ISSUE((t + 1) * 32, (t + 1) & 1); CP_COMMIT(); CP_WAIT(1); }
        else                { CP_WAIT(0); }
        __syncthreads();

        const uint32_t* Acur = &As[(t & 1) * ABUF];
        const uint32_t* Bcur = &Bs[(t & 1) * ABUF];
#pragma unroll
        for (int ks = 0; ks < 4; ks++) {
            uint32_t af[4][4];
#pragma unroll
            for (int mi = 0; mi < 4; mi++) {
                int r = wm * 64 + mi * 16 + lg, c = ks * 8 + lt;
                af[mi][0] = Acur[r * GLDA + c];
                af[mi][1] = Acur[(r + 8) * GLDA + c];
                af[mi][2] = Acur[r * GLDA + c + 4];
                af[mi][3] = Acur[(r + 8) * GLDA + c + 4];
            }
#pragma unroll
            for (int ni = 0; ni < 4; ni++) {
                int cb = wn * 32 + ni * 8 + lg, ck = ks * 8 + lt;
                uint32_t b0 = Bcur[cb * GLDA + ck];
                uint32_t b1 = Bcur[cb * GLDA + ck + 4];
#pragma unroll
                for (int mi = 0; mi < 4; mi++)
                    mma_tf32(acc[mi][ni], af[mi][0], af[mi][1], af[mi][2], af[mi][3], b0, b1);
            }
        }
        __syncthreads();   // close reads of buf t&1 before it is re-issued
    }
#undef ISSUE

    // epilogue: write tf32-rounded (consumers treat these as tf32 anyway)
#pragma unroll
    for (int mi = 0; mi < 4; mi++) {
        int row = blockIdx.y * 128 + wm * 64 + mi * 16 + lg;
#pragma unroll
        for (int ni = 0; ni < 4; ni++) {
            int col = cb0 * 128 + wn * 32 + ni * 8 + lt * 2;
            uint2 u0 = {f2tf32(acc[mi][ni][0]), f2tf32(acc[mi][ni][1])};
            uint2 u1 = {f2tf32(acc[mi][ni][2]), f2tf32(acc[mi][ni][3])};
            *(uint2*)(C + (size_t)row * N + col) = u0;
            *(uint2*)(C + (size_t)(row + 8) * N + col) = u1;
        }
    }
}

// ---------------------------------------------------------------------------
// tf32 GEMM NN, cp.async edition: C[M,N] = A[M,K] * B[K,N].
// A (=AO) pre-rounded by attention epilogue; B (=W_O) pre-rounded.
// Output written UNROUNDED (final result). B tile row-major [32][132].
// ---------------------------------------------------------------------------
#define GLDB 132
#define BBUF (32 * GLDB)

__global__ __launch_bounds__(256)
void gemm_nn_tf32(const float* __restrict__ A, const float* __restrict__ B,
                  float* __restrict__ C, int M, int N, int K) {
    extern __shared__ uint32_t sm[];
    uint32_t* As = sm;
    uint32_t* Bs = sm + 2 * ABUF;
    const uint32_t saA = smem_u32(sm);
    const uint32_t saB = saA + 2 * ABUF * 4;

    const int tid = threadIdx.x, lane = tid & 31, wid = tid >> 5;
    const int wm = wid >> 2, wn = wid & 3;
    const int lg = lane >> 2, lt = lane & 3;

    const float* Ab = A + (size_t)(blockIdx.y * 128) * K;
    const float* Bb = B + blockIdx.x * 128;

    float acc[4][4][4];
#pragma unroll
    for (int i = 0; i < 4; i++)
#pragma unroll
        for (int j = 0; j < 4; j++)
#pragma unroll
            for (int r = 0; r < 4; r++) acc[i][j][r] = 0.f;

#define ISSUE(k0, buf)                                                          \
    {                                                                           \
        _Pragma("unroll") for (int i = 0; i < 4; i++) {                         \
            int idx = tid + i * 256;                                            \
            int rw = idx >> 3, cq = (idx & 7) * 4;                              \
            cp_async16(saA + (buf) * (ABUF * 4) + (uint32_t)(rw * GLDA + cq) * 4, \
                       Ab + (size_t)rw * K + (k0) + cq);                        \
            int bk = idx >> 5, bc = (idx & 31) * 4;                             \
            cp_async16(saB + (buf) * (BBUF * 4) + (uint32_t)(bk * GLDB + bc) * 4, \
                       Bb + (size_t)((k0) + bk) * N + bc);                      \
        }                                                                       \
    }

    ISSUE(0, 0); CP_COMMIT();

    const int nsteps = K / 32;
    for (int t = 0; t < nsteps; t++) {
        if (t + 1 < nsteps) { ISSUE((t + 1) * 32, (t + 1) & 1); CP_COMMIT(); CP_WAIT(1); }
        else                { CP_WAIT(0); }
        __syncthreads();

        const uint32_t* Acur = &As[(t & 1) * ABUF];
        const uint32_t* Bcur = &Bs[(t & 1) * BBUF];
#pragma unroll
        for (int ks = 0; ks < 4; ks++) {
            uint32_t af[4][4];
#pragma unroll
            for (int mi = 0; mi < 4; mi++) {
                int r = wm * 64 + mi * 16 + lg, c = ks * 8 + lt;
                af[mi][0] = Acur[r * GLDA + c];
                af[mi][1] = Acur[(r + 8) * GLDA + c];
                af[mi][2] = Acur[r * GLDA + c + 4];
                af[mi][3] = Acur[(r + 8) * GLDA + c + 4];
            }
#pragma unroll
            for (int ni = 0; ni < 4; ni++) {
                int cn = wn * 32 + ni * 8 + lg;
                uint32_t b0 = Bcur[(ks * 8 + lt) * GLDB + cn];
                uint32_t b1 = Bcur[(ks * 8 + lt + 4) * GLDB + cn];
#pragma unroll
                for (int mi = 0; mi < 4; mi++)
                    mma_tf32(acc[mi][ni], af[mi][0], af[mi][1], af[mi][2], af[mi][3], b0, b1);
            }
        }
        __syncthreads();
    }
#undef ISSUE

#pragma unroll
    for (int mi = 0; mi < 4; mi++) {
        int row = blockIdx.y * 128 + wm * 64 + mi * 16 + lg;
#pragma unroll
        for (int ni = 0; ni < 4; ni++) {
            int col = blockIdx.x * 128 + wn * 32 + ni * 8 + lt * 2;
            *(float2*)(C + (size_t)row * N + col) = make_float2(acc[mi][ni][0], acc[mi][ni][1]);
            *(float2*)(C + (size_t)(row + 8) * N + col) = make_float2(acc[mi][ni][2], acc[mi][ni][3]);
        }
    }
}

// ---------------------------------------------------------------------------
// Flash attention, tf32 mma.sync. BM=128 Q rows, K tile 64.
// 256 thr (8 warps); warp w owns q-rows [w*16, w*16+16). Grid (S/128, NH, B).
// Q/K/V arrive tf32-rounded -> Q frags direct (x0.125 exponent-only),
// K/V tiles via cp.async (no cvt, no STS). P still cvt'd (fresh values).
// AO written tf32-rounded for the O-projection.
// SMEM: Ks[64][68] Vs[64][68] Ps[128][68] = 69,632 B -> 2 CTAs/SM.
// LPT: qt = gridDim.x-1-blockIdx.x.
// ---------------------------------------------------------------------------
#define ALDS 68
#define KVT (64 * ALDS)
#define NEG_BIG (-1e30f)

__global__ __launch_bounds__(256, 2)
void attn_tf32(const float* __restrict__ Q, const float* __restrict__ K,
               const float* __restrict__ V, float* __restrict__ O) {
    extern __shared__ uint32_t sm[];
    uint32_t* Ks = sm;              // [64*ALDS]
    uint32_t* Vs = sm + KVT;        // [64*ALDS]
    uint32_t* Ps = sm + 2 * KVT;    // [128*ALDS]
    const uint32_t ksA = smem_u32(sm);
    const uint32_t vsA = ksA + KVT * 4;

    const int qt = gridDim.x - 1 - blockIdx.x;   // LPT: heavy first
    const int h = blockIdx.y, b = blockIdx.z;
    const int kvh = h >> 2;
    const int tid = threadIdx.x, lane = tid & 31, wid = tid >> 5;
    const int lg = lane >> 2, lt = lane & 3;
    const int q0 = wid * 16;

    const float* Qg = Q + ((size_t)(b * SEQ + qt * 128)) * (NH * DH) + h * DH;
    const float* Kg = K + ((size_t)b * SEQ) * (NKV * DH) + kvh * DH;
    const float* Vg = V + ((size_t)b * SEQ) * (NKV * DH) + kvh * DH;

    const int ldr = tid >> 4;            // 0..15
    const int ldc = (tid & 15) * 4;      // word col (16B aligned)

    // Q fragments: pre-rounded tf32; x0.125 is exponent-only (stays tf32)
    uint32_t qf[8][4];
    {
        const float* q0p = Qg + (size_t)(q0 + lg) * (NH * DH);
        const float* q1p = Qg + (size_t)(q0 + lg + 8) * (NH * DH);
#pragma unroll
        for (int ks = 0; ks < 8; ks++) {
            int c = ks * 8 + lt;
            qf[ks][0] = __float_as_uint(__ldg(q0p + c) * 0.125f);
            qf[ks][1] = __float_as_uint(__ldg(q1p + c) * 0.125f);
            qf[ks][2] = __float_as_uint(__ldg(q0p + c + 4) * 0.125f);
            qf[ks][3] = __float_as_uint(__ldg(q1p + c + 4) * 0.125f);
        }
    }

    float m0 = NEG_BIG, m1 = NEG_BIG, l0 = 0.f, l1 = 0.f;
    float acc[8][4];
#pragma unroll
    for (int d = 0; d < 8; d++)
#pragma unroll
        for (int r = 0; r < 4; r++) acc[d][r] = 0.f;

    const int ktmax = 2 * qt + 1;
    const int warp_qlast = qt * 128 + q0 + 15;

    for (int kt = 0; kt <= ktmax; kt++) {
        // K,V tile kt via cp.async (4+4 x 16B per thread)
#pragma unroll
        for (int i = 0; i < 4; i++) {
            int r = ldr + i * 16;
            uint32_t so = (uint32_t)(r * ALDS + ldc) * 4;
            cp_async16(ksA + so, Kg + (size_t)(kt * 64 + r) * (NKV * DH) + ldc);
            cp_async16(vsA + so, Vg + (size_t)(kt * 64 + r) * (NKV * DH) + ldc);
        }
        CP_COMMIT();
        CP_WAIT(0);
        __syncthreads();

        if (kt * 64 <= warp_qlast) {      // tile not fully masked for this warp
            float sc[8][4];
#pragma unroll
            for (int ni = 0; ni < 8; ni++)
#pragma unroll
                for (int r = 0; r < 4; r++) sc[ni][r] = 0.f;
#pragma unroll
            for (int ks = 0; ks < 8; ks++) {
#pragma unroll
                for (int ni = 0; ni < 8; ni++) {
                    int rB = ni * 8 + lg, cB = ks * 8 + lt;
                    uint32_t b0 = Ks[rB * ALDS + cB];
                    uint32_t b1 = Ks[rB * ALDS + cB + 4];
                    mma_tf32(sc[ni], qf[ks][0], qf[ks][1], qf[ks][2], qf[ks][3], b0, b1);
                }
            }

            if (kt * 64 + 63 > qt * 128 + q0) {   // diagonal region: mask
                int r0g = qt * 128 + q0 + lg, r1g = r0g + 8;
#pragma unroll
                for (int ni = 0; ni < 8; ni++) {
                    int cg = kt * 64 + ni * 8 + lt * 2;
                    if (cg > r0g) sc[ni][0] = NEG_BIG;
                    if (cg + 1 > r0g) sc[ni][1] = NEG_BIG;
                    if (cg > r1g) sc[ni][2] = NEG_BIG;
                    if (cg + 1 > r1g) sc[ni][3] = NEG_BIG;
                }
            }

            // online softmax: rows (q0+lg), (q0+lg+8)
            float mx0 = NEG_BIG, mx1 = NEG_BIG;
#pragma unroll
            for (int ni = 0; ni < 8; ni++) {
                mx0 = fmaxf(mx0, fmaxf(sc[ni][0], sc[ni][1]));
                mx1 = fmaxf(mx1, fmaxf(sc[ni][2], sc[ni][3]));
            }
            mx0 = fmaxf(mx0, __shfl_xor_sync(0xffffffffu, mx0, 1));
            mx0 = fmaxf(mx0, __shfl_xor_sync(0xffffffffu, mx0, 2));
            mx1 = fmaxf(mx1, __shfl_xor_sync(0xffffffffu, mx1, 1));
            mx1 = fmaxf(mx1, __shfl_xor_sync(0xffffffffu, mx1, 2));
            float nm0 = fmaxf(m0, mx0), nm1 = fmaxf(m1, mx1);
            float corr0 = __expf(m0 - nm0), corr1 = __expf(m1 - nm1);
            m0 = nm0; m1 = nm1;

            float s0 = 0.f, s1 = 0.f;
            int pr0 = (q0 + lg) * ALDS, pr1 = (q0 + lg + 8) * ALDS;
#pragma unroll
            for (int ni = 0; ni < 8; ni++) {
                int c = ni * 8 + lt * 2;
                float p00 = __expf(sc[ni][0] - m0), p01 = __expf(sc[ni][1] - m0);
                float p10 = __expf(sc[ni][2] - m1), p11 = __expf(sc[ni][3] - m1);
                s0 += p00 + p01; s1 += p10 + p11;
                uint2 u0 = {f2tf32(p00), f2tf32(p01)};
                uint2 u1 = {f2tf32(p10), f2tf32(p11)};
                *(uint2*)&Ps[pr0 + c] = u0;
                *(uint2*)&Ps[pr1 + c] = u1;
            }
            s0 += __shfl_xor_sync(0xffffffffu, s0, 1);
            s0 += __shfl_xor_sync(0xffffffffu, s0, 2);
            s1 += __shfl_xor_sync(0xffffffffu, s1, 1);
            s1 += __shfl_xor_sync(0xffffffffu, s1, 2);
            l0 = l0 * corr0 + s0;
            l1 = l1 * corr1 + s1;
#pragma unroll
            for (int d = 0; d < 8; d++) {
                acc[d][0] *= corr0; acc[d][1] *= corr0;
                acc[d][2] *= corr1; acc[d][3] *= corr1;
            }
            __syncwarp();

            // acc += P V  (P rows warp-private)
#pragma unroll
            for (int ks = 0; ks < 8; ks++) {
                int rA = q0 + lg, cA = ks * 8 + lt;
                uint32_t a0 = Ps[rA * ALDS + cA];
                uint32_t a1 = Ps[(rA + 8) * ALDS + cA];
                uint32_t a2 = Ps[rA * ALDS + cA + 4];
                uint32_t a3 = Ps[(rA + 8) * ALDS + cA + 4];
#pragma unroll
                for (int di = 0; di < 8; di++) {
                    int cn = di * 8 + lg;
                    uint32_t b0 = Vs[(ks * 8 + lt) * ALDS + cn];
                    uint32_t b1 = Vs[(ks * 8 + lt + 4) * ALDS + cn];
                    mma_tf32(acc[di], a0, a1, a2, a3, b0, b1);
                }
            }
        }
        __syncthreads();
    }

    // epilogue: normalize, round to tf32 (feeds the O-projection)
    float inv0 = 1.f / l0, inv1 = 1.f / l1;
    float* Og = O + ((size_t)(b * SEQ + qt * 128 + q0 + lg)) * (NH * DH) + h * DH;
#pragma unroll
    for (int di = 0; di < 8; di++) {
        int c = di * 8 + lt * 2;
        uint2 u0 = {f2tf32(acc[di][0] * inv0), f2tf32(acc[di][1] * inv0)};
        uint2 u1 = {f2tf32(acc[di][2] * inv1), f2tf32(acc[di][3] * inv1)};
        *(uint2*)(Og + c) = u0;
        *(uint2*)(Og + (size_t)8 * (NH * DH) + c) = u1;
    }
}

// ---------------------------------------------------------------------------
// kernel_launch
// ---------------------------------------------------------------------------
extern "C" void kernel_launch(void* const* d_in, const int* in_sizes, int n_in,
                              void* d_out, int out_size) {
    const float* residual = (const float*)d_in[0];
    const float* WQ = (const float*)d_in[1];
    const float* WK = (const float*)d_in[2];
    const float* WV = (const float*)d_in[3];
    const float* WO = (const float*)d_in[4];
    float* out = (float*)d_out;

    float *Qb, *Kb, *Vb, *AOb, *RESb, *WQb, *WKb, *WVb, *WOb;
    cudaGetSymbolAddress((void**)&Qb, g_Q);
    cudaGetSymbolAddress((void**)&Kb, g_K);
    cudaGetSymbolAddress((void**)&Vb, g_V);
    cudaGetSymbolAddress((void**)&AOb, g_AO);
    cudaGetSymbolAddress((void**)&RESb, g_RES);
    cudaGetSymbolAddress((void**)&WQb, g_WQr);
    cudaGetSymbolAddress((void**)&WKb, g_WKr);
    cudaGetSymbolAddress((void**)&WVb, g_WVr);
    cudaGetSymbolAddress((void**)&WOb, g_WOr);

    size_t smem_nt = (size_t)4 * ABUF * 4;
    size_t smem_nn = ((size_t)2 * ABUF + 2 * BBUF) * 4;
    size_t smem_at = ((size_t)2 * KVT + 128 * ALDS) * 4;   // 69,632 B
    static int attrs_set = 0;
    if (!attrs_set) {
        cudaFuncSetAttribute(gemm_qkv_tf32, cudaFuncAttributeMaxDynamicSharedMemorySize, (int)smem_nt);
        cudaFuncSetAttribute(gemm_nn_tf32, cudaFuncAttributeMaxDynamicSharedMemorySize, (int)smem_nn);
        cudaFuncSetAttribute(attn_tf32, cudaFuncAttributeMaxDynamicSharedMemorySize, (int)smem_at);
        attrs_set = 1;
    }

    // pre-round inputs to tf32 (rna) so hot loops skip cvt and use cp.async
    round_tf32<<<(T_TOK * DMODEL) / 1024, 256>>>(residual, RESb);
    round_tf32<<<(NH * DH * DMODEL) / 1024, 256>>>(WQ, WQb);
    round_tf32<<<(NKV * DH * DMODEL) / 1024, 256>>>(WK, WKb);
    round_tf32<<<(NKV * DH * DMODEL) / 1024, 256>>>(WV, WVb);
    round_tf32<<<(NH * DH * DMODEL) / 1024, 256>>>(WO, WOb);

    gemm_qkv_tf32<<<dim3(24, T_TOK / 128), 256, smem_nt>>>(
        RESb, WQb, WKb, WVb, Qb, Kb, Vb);

    attn_tf32<<<dim3(SEQ / 128, NH, 2), 256, smem_at>>>(Qb, Kb, Vb, AOb);

    gemm_nn_tf32<<<dim3(DMODEL / 128, T_TOK / 128), 256, smem_nn>>>(
        AOb, WOb, out, T_TOK, DMODEL, DMODEL);
}